// round 1
// baseline (speedup 1.0000x reference)
#include <cuda_runtime.h>
#include <math.h>

#define Bb 2
#define Tt 2048
#define Cc 1024
#define Hh 16
#define Dd 64

// Scratch (allocation-free: __device__ globals)
__device__ float g_xn [Bb*Tt*Cc];      // ln1 out, later ln2 out
__device__ float g_q  [Bb*Tt*Cc];      // Q  (row b*T+t, col h*64+d)
__device__ float g_v  [Bb*Tt*Cc];      // V
__device__ float g_att[Bb*Tt*Cc];      // attention output [b,t,c]
__device__ float g_x1 [Bb*Tt*Cc];      // x + attn proj (residual)
__device__ float g_h  [Bb*Tt*4*Cc];    // gelu(mlp1)

// ---------------------------------------------------------------- block reduce
__device__ __forceinline__ float block_sum(float v, volatile float* red){
    #pragma unroll
    for (int o = 16; o; o >>= 1) v += __shfl_xor_sync(0xffffffffu, v, o);
    int lane = threadIdx.x & 31, w = threadIdx.x >> 5;
    if (lane == 0) red[w] = v;
    __syncthreads();
    if (w == 0){
        v = (lane < 8) ? red[lane] : 0.f;
        #pragma unroll
        for (int o = 4; o; o >>= 1) v += __shfl_xor_sync(0xffffffffu, v, o);
    }
    return v;  // valid in warp 0 (thread 0 broadcasts via smem)
}

// ---------------------------------------------------------------- LayerNorm
__global__ void ln_kernel(const float* __restrict__ x, const float* __restrict__ g,
                          const float* __restrict__ b, float* __restrict__ out){
    __shared__ float red[8];
    __shared__ float s_mu, s_rs;
    int row = blockIdx.x, tid = threadIdx.x;   // 256 threads, 4 floats each
    const float4 v = ((const float4*)(x + (size_t)row * Cc))[tid];
    float s = v.x + v.y + v.z + v.w;
    s = block_sum(s, red);
    if (tid == 0) s_mu = s * (1.0f / Cc);
    __syncthreads();
    float mu = s_mu;
    float dx = v.x - mu, dy = v.y - mu, dz = v.z - mu, dw = v.w - mu;
    float sq = dx*dx + dy*dy + dz*dz + dw*dw;
    sq = block_sum(sq, red);
    if (tid == 0) s_rs = rsqrtf(sq * (1.0f / Cc) + 1e-5f);
    __syncthreads();
    float rs = s_rs;
    float4 gg = ((const float4*)g)[tid], bb = ((const float4*)b)[tid];
    float4 o;
    o.x = dx * rs * gg.x + bb.x;
    o.y = dy * rs * gg.y + bb.y;
    o.z = dz * rs * gg.z + bb.z;
    o.w = dw * rs * gg.w + bb.w;
    ((float4*)(out + (size_t)row * Cc))[tid] = o;
}

// ---------------------------------------------------------------- fp32 GEMM
// out[M,N] = A[M,K] @ W[K,N] + bias (+ resid) (gelu optional)
// grid (N/64, M/64), block 256, 4x4 per thread, BK=16.
__global__ void gemm_kernel(const float* __restrict__ A, int lda,
                            const float* __restrict__ W, int ldw,
                            const float* __restrict__ bias,
                            const float* __restrict__ resid,
                            float* __restrict__ out,
                            int N, int K, int do_gelu){
    __shared__ float As[16][68];   // [k][m], padded
    __shared__ float Bs[16][64];   // [k][n]
    const int tid = threadIdx.x;
    const int tx = tid & 15, ty = tid >> 4;
    const int row0 = blockIdx.y * 64, col0 = blockIdx.x * 64;
    const int ar = tid >> 2, ak = (tid & 3) << 2;
    const int bk = tid >> 4, bn = (tid & 15) << 2;
    const float* Ap = A + (size_t)(row0 + ar) * lda + ak;
    const float* Wp = W + (size_t)bk * ldw + col0 + bn;
    float acc[4][4] = {};
    for (int k0 = 0; k0 < K; k0 += 16){
        float4 av = *(const float4*)(Ap + k0);
        float4 wv = *(const float4*)(Wp + (size_t)k0 * ldw);
        As[ak+0][ar] = av.x; As[ak+1][ar] = av.y; As[ak+2][ar] = av.z; As[ak+3][ar] = av.w;
        *(float4*)&Bs[bk][bn] = wv;
        __syncthreads();
        #pragma unroll
        for (int k = 0; k < 16; k++){
            float4 a  = *(const float4*)&As[k][ty << 2];
            float4 bq = *(const float4*)&Bs[k][tx << 2];
            float af[4] = {a.x, a.y, a.z, a.w};
            float bf[4] = {bq.x, bq.y, bq.z, bq.w};
            #pragma unroll
            for (int i = 0; i < 4; i++)
                #pragma unroll
                for (int j = 0; j < 4; j++)
                    acc[i][j] = fmaf(af[i], bf[j], acc[i][j]);
        }
        __syncthreads();
    }
    int c = col0 + (tx << 2);
    float4 bb = *(const float4*)&bias[c];
    #pragma unroll
    for (int i = 0; i < 4; i++){
        int r = row0 + (ty << 2) + i;
        float4 o;
        o.x = acc[i][0] + bb.x; o.y = acc[i][1] + bb.y;
        o.z = acc[i][2] + bb.z; o.w = acc[i][3] + bb.w;
        if (resid){
            float4 rr = *(const float4*)&resid[(size_t)r * N + c];
            o.x += rr.x; o.y += rr.y; o.z += rr.z; o.w += rr.w;
        }
        if (do_gelu){
            o.x = 0.5f * o.x * (1.f + erff(o.x * 0.70710678118f));
            o.y = 0.5f * o.y * (1.f + erff(o.y * 0.70710678118f));
            o.z = 0.5f * o.z * (1.f + erff(o.z * 0.70710678118f));
            o.w = 0.5f * o.w * (1.f + erff(o.w * 0.70710678118f));
        }
        *(float4*)&out[(size_t)r * N + c] = o;
    }
}

// ---------------------------------------------------------------- Attention
// scores = lif_rate(gain*(Q·E) + bias)/8 ; causal ; softmax ; @V
// Key insight: score in [0, 62.5] => exp() never overflows fp32 => simple
// streaming numerator/denominator accumulation, no online max rescaling.
// grid (T/64, B*H), block 256 (16x16), 4x4 scores per thread per s-tile.
#define ATTN_SMEM ((2*64*68 + 64*64 + 64*68) * 4)

__global__ void attn_kernel(const float* __restrict__ Q, const float* __restrict__ V,
                            const float* __restrict__ E, const float* __restrict__ gain,
                            const float* __restrict__ bias, float* __restrict__ out){
    extern __shared__ float sm[];
    float* Qt = sm;                         // [64 d][68] d-major: Qt[d*68 + r]
    float* Et = sm + 64*68;                 // [64 d][68] d-major: Et[d*68 + s]
    float* Vs = sm + 2*64*68;               // [64 s][64 d]
    float* Ps = sm + 2*64*68 + 64*64;       // [64 r][68 s]
    const int tid = threadIdx.x;
    const int tx = tid & 15, ty = tid >> 4;
    const int bh = blockIdx.y, b = bh >> 4, h = bh & 15;
    const int t0 = blockIdx.x << 6;
    const int lr = tid >> 2, lc = (tid & 3) << 4;

    // load Q tile (64 rows x 64 d) transposed to d-major
    {
        const float* qp = Q + ((size_t)(b*Tt + t0 + lr)) * Cc + h*Dd + lc;
        #pragma unroll
        for (int q = 0; q < 4; q++){
            float4 v4 = *(const float4*)(qp + q*4);
            Qt[(lc+q*4+0)*68 + lr] = v4.x;
            Qt[(lc+q*4+1)*68 + lr] = v4.y;
            Qt[(lc+q*4+2)*68 + lr] = v4.z;
            Qt[(lc+q*4+3)*68 + lr] = v4.w;
        }
    }
    float gv[4], bv[4];
    #pragma unroll
    for (int i = 0; i < 4; i++){
        int t = t0 + (ty << 2) + i;
        gv[i] = gain[h*Tt + t];
        bv[i] = bias[h*Tt + t];
    }
    float acc[4][4] = {};
    float rsum[4] = {};

    for (int s0 = 0; s0 <= t0; s0 += 64){
        // load E tile (transposed) and V tile
        {
            const float* ep = E + ((size_t)(h*Tt + s0 + lr)) * Dd + lc;
            #pragma unroll
            for (int q = 0; q < 4; q++){
                float4 v4 = *(const float4*)(ep + q*4);
                Et[(lc+q*4+0)*68 + lr] = v4.x;
                Et[(lc+q*4+1)*68 + lr] = v4.y;
                Et[(lc+q*4+2)*68 + lr] = v4.z;
                Et[(lc+q*4+3)*68 + lr] = v4.w;
            }
            const float* vp = V + ((size_t)(b*Tt + s0 + lr)) * Cc + h*Dd + lc;
            #pragma unroll
            for (int q = 0; q < 4; q++)
                *(float4*)&Vs[lr*64 + lc + q*4] = *(const float4*)(vp + q*4);
        }
        __syncthreads();

        // P = exp(lif(gain*Q·E + bias)/8), causal-masked
        float dot[4][4] = {};
        #pragma unroll 8
        for (int d = 0; d < 64; d++){
            float4 qa = *(const float4*)&Qt[d*68 + (ty << 2)];
            float4 eb = *(const float4*)&Et[d*68 + (tx << 2)];
            float qf[4] = {qa.x, qa.y, qa.z, qa.w};
            float ef[4] = {eb.x, eb.y, eb.z, eb.w};
            #pragma unroll
            for (int i = 0; i < 4; i++)
                #pragma unroll
                for (int j = 0; j < 4; j++)
                    dot[i][j] = fmaf(qf[i], ef[j], dot[i][j]);
        }
        #pragma unroll
        for (int i = 0; i < 4; i++){
            int t = t0 + (ty << 2) + i;
            #pragma unroll
            for (int j = 0; j < 4; j++){
                int s = s0 + (tx << 2) + j;
                float p = 0.f;
                if (s <= t){
                    float I = fmaf(gv[i], dot[i][j], bv[i]);
                    if (I > 1.0000001f){
                        float rr = 1.0f / (0.002f - 0.02f * log1pf(-1.0f / I));
                        p = expf(rr * 0.125f);
                    } else {
                        p = 1.0f;   // exp(0): lif rate 0
                    }
                }
                Ps[((ty<<2)+i)*68 + (tx<<2)+j] = p;
            }
        }
        __syncthreads();

        // acc += P @ V ; rsum += row-sums of P
        #pragma unroll 4
        for (int s = 0; s < 64; s++){
            float4 vvv = *(const float4*)&Vs[s*64 + (tx << 2)];
            float vf[4] = {vvv.x, vvv.y, vvv.z, vvv.w};
            #pragma unroll
            for (int i = 0; i < 4; i++){
                float pv = Ps[((ty<<2)+i)*68 + s];
                rsum[i] += pv;
                #pragma unroll
                for (int j = 0; j < 4; j++)
                    acc[i][j] = fmaf(pv, vf[j], acc[i][j]);
            }
        }
        __syncthreads();
    }

    #pragma unroll
    for (int i = 0; i < 4; i++){
        float inv = 1.0f / rsum[i];  // diagonal always unmasked => rsum >= 1
        float4 o;
        o.x = acc[i][0]*inv; o.y = acc[i][1]*inv;
        o.z = acc[i][2]*inv; o.w = acc[i][3]*inv;
        int t = t0 + (ty << 2) + i;
        *(float4*)&out[((size_t)(b*Tt + t)) * Cc + h*Dd + (tx << 2)] = o;
    }
}

// ---------------------------------------------------------------- launch
extern "C" void kernel_launch(void* const* d_in, const int* in_sizes, int n_in,
                              void* d_out, int out_size){
    const float* x      = (const float*)d_in[0];
    const float* ln1_g  = (const float*)d_in[1];
    const float* ln1_b  = (const float*)d_in[2];
    const float* qkv_w  = (const float*)d_in[3];
    const float* qkv_b  = (const float*)d_in[4];
    const float* out_w  = (const float*)d_in[5];
    const float* out_b  = (const float*)d_in[6];
    const float* ln2_g  = (const float*)d_in[7];
    const float* ln2_b  = (const float*)d_in[8];
    const float* mlp_w1 = (const float*)d_in[9];
    const float* mlp_b1 = (const float*)d_in[10];
    const float* mlp_w2 = (const float*)d_in[11];
    const float* mlp_b2 = (const float*)d_in[12];
    const float* enc    = (const float*)d_in[13];
    const float* gain   = (const float*)d_in[14];
    const float* battn  = (const float*)d_in[15];
    float* outp = (float*)d_out;

    float *xn, *q, *v, *att, *x1, *hbuf;
    cudaGetSymbolAddress((void**)&xn,   g_xn);
    cudaGetSymbolAddress((void**)&q,    g_q);
    cudaGetSymbolAddress((void**)&v,    g_v);
    cudaGetSymbolAddress((void**)&att,  g_att);
    cudaGetSymbolAddress((void**)&x1,   g_x1);
    cudaGetSymbolAddress((void**)&hbuf, g_h);

    cudaFuncSetAttribute(attn_kernel, cudaFuncAttributeMaxDynamicSharedMemorySize, ATTN_SMEM);

    const int M = Bb * Tt;   // 4096

    // 1) LN1
    ln_kernel<<<M, 256>>>(x, ln1_g, ln1_b, xn);
    // 2) Q = xn @ qkv_w[:, 0:1024]      (K columns are unused by the reference!)
    gemm_kernel<<<dim3(Cc/64, M/64), 256>>>(xn, Cc, qkv_w,        3*Cc, qkv_b,        nullptr, q, Cc, Cc, 0);
    // 3) V = xn @ qkv_w[:, 2048:3072]
    gemm_kernel<<<dim3(Cc/64, M/64), 256>>>(xn, Cc, qkv_w + 2*Cc, 3*Cc, qkv_b + 2*Cc, nullptr, v, Cc, Cc, 0);
    // 4) attention
    attn_kernel<<<dim3(Tt/64, Bb*Hh), 256, ATTN_SMEM>>>(q, v, enc, gain, battn, att);
    // 5) x1 = x + att @ out_w + out_b
    gemm_kernel<<<dim3(Cc/64, M/64), 256>>>(att, Cc, out_w, Cc, out_b, x, x1, Cc, Cc, 0);
    // 6) LN2
    ln_kernel<<<M, 256>>>(x1, ln2_g, ln2_b, xn);
    // 7) h = gelu(xn @ mlp_w1 + b1)
    gemm_kernel<<<dim3(4*Cc/64, M/64), 256>>>(xn, Cc, mlp_w1, 4*Cc, mlp_b1, nullptr, hbuf, 4*Cc, Cc, 1);
    // 8) out = x1 + h @ mlp_w2 + b2
    gemm_kernel<<<dim3(Cc/64, M/64), 256>>>(hbuf, 4*Cc, mlp_w2, Cc, mlp_b2, x1, outp, Cc, 4*Cc, 0);
}

// round 2
// speedup vs baseline: 2.0039x; 2.0039x over previous
#include <cuda_runtime.h>
#include <math.h>
#include <stdint.h>

#define Bb 2
#define Tt 2048
#define Cc 1024
#define Hh 16
#define Dd 64

// Scratch (allocation-free: __device__ globals)
__device__ float g_xn [Bb*Tt*Cc];
__device__ float g_q  [Bb*Tt*Cc];
__device__ float g_v  [Bb*Tt*Cc];
__device__ float g_att[Bb*Tt*Cc];
__device__ float g_x1 [Bb*Tt*Cc];
__device__ float g_h  [Bb*Tt*4*Cc];

// ---------------------------------------------------------------- block reduce
__device__ __forceinline__ float block_sum(float v, volatile float* red){
    #pragma unroll
    for (int o = 16; o; o >>= 1) v += __shfl_xor_sync(0xffffffffu, v, o);
    int lane = threadIdx.x & 31, w = threadIdx.x >> 5;
    if (lane == 0) red[w] = v;
    __syncthreads();
    if (w == 0){
        v = (lane < 8) ? red[lane] : 0.f;
        #pragma unroll
        for (int o = 4; o; o >>= 1) v += __shfl_xor_sync(0xffffffffu, v, o);
    }
    return v;
}

// ---------------------------------------------------------------- LayerNorm
__global__ void ln_kernel(const float* __restrict__ x, const float* __restrict__ g,
                          const float* __restrict__ b, float* __restrict__ out){
    __shared__ float red[8];
    __shared__ float s_mu, s_rs;
    int row = blockIdx.x, tid = threadIdx.x;
    const float4 v = ((const float4*)(x + (size_t)row * Cc))[tid];
    float s = v.x + v.y + v.z + v.w;
    s = block_sum(s, red);
    if (tid == 0) s_mu = s * (1.0f / Cc);
    __syncthreads();
    float mu = s_mu;
    float dx = v.x - mu, dy = v.y - mu, dz = v.z - mu, dw = v.w - mu;
    float sq = dx*dx + dy*dy + dz*dz + dw*dw;
    sq = block_sum(sq, red);
    if (tid == 0) s_rs = rsqrtf(sq * (1.0f / Cc) + 1e-5f);
    __syncthreads();
    float rs = s_rs;
    float4 gg = ((const float4*)g)[tid], bb = ((const float4*)b)[tid];
    float4 o;
    o.x = dx * rs * gg.x + bb.x;
    o.y = dy * rs * gg.y + bb.y;
    o.z = dz * rs * gg.z + bb.z;
    o.w = dw * rs * gg.w + bb.w;
    ((float4*)(out + (size_t)row * Cc))[tid] = o;
}

// ---------------------------------------------------------------- tf32 tensor GEMM
// out[M,N] = A[M,K] @ W[K,N] + bias (+resid) (+gelu). BM=BN=128, BK=16.
// 256 thr, 8 warps as 2(m)x4(n), warp tile 64x32, mma.m16n8k8 tf32.
#define GBM 128
#define GBN 128
#define GBK 16
#define ASTR 20   // smem row stride (floats) for A[m][k]  -> 5*row mod 8 permutation
#define BSTR 20   // smem row stride for B^T[n][k]

__device__ __forceinline__ float to_tf32(float x){
    float r; asm("cvt.rna.tf32.f32 %0, %1;" : "=f"(r) : "f"(x)); return r;
}

__global__ __launch_bounds__(256) void gemm_tc(
        const float* __restrict__ A, int lda,
        const float* __restrict__ W, int ldw,
        const float* __restrict__ bias,
        const float* __restrict__ resid,
        float* __restrict__ out,
        int N, int K, int do_gelu){
    __shared__ float As[2][GBM*ASTR];
    __shared__ float Bs[2][GBN*BSTR];
    const int tid = threadIdx.x;
    const int lane = tid & 31, w = tid >> 5;
    const int warpM = (w & 1) * 64, warpN = (w >> 1) * 32;
    const int row0 = blockIdx.y * GBM, col0 = blockIdx.x * GBN;

    // A staging: thread -> (m = tid/2, k0 = (tid&1)*8), 2x float4
    const int am = tid >> 1, ak = (tid & 1) * 8;
    const float* Ap = A + (size_t)(row0 + am) * lda + ak;
    // B staging: thread -> (n = (w&3)*32 + lane), k rows bk0+{0..3}, bk0+8+{0..3}
    const int bn = (w & 3) * 32 + lane;
    const int bk0 = (w >> 2) * 4;
    const float* Bp = W + (size_t)bk0 * ldw + col0 + bn;

    float4 ra0, ra1;
    float rb[8];

    auto ldg_tile = [&](int kt){
        ra0 = *(const float4*)(Ap + kt);
        ra1 = *(const float4*)(Ap + kt + 4);
        #pragma unroll
        for (int j = 0; j < 4; j++){
            rb[j]     = Bp[(size_t)(kt + j) * ldw];
            rb[4 + j] = Bp[(size_t)(kt + 8 + j) * ldw];
        }
    };
    auto sts_tile = [&](int buf){
        float4 c0 = make_float4(to_tf32(ra0.x), to_tf32(ra0.y), to_tf32(ra0.z), to_tf32(ra0.w));
        float4 c1 = make_float4(to_tf32(ra1.x), to_tf32(ra1.y), to_tf32(ra1.z), to_tf32(ra1.w));
        *(float4*)&As[buf][am * ASTR + ak]     = c0;
        *(float4*)&As[buf][am * ASTR + ak + 4] = c1;
        float4 b0 = make_float4(to_tf32(rb[0]), to_tf32(rb[1]), to_tf32(rb[2]), to_tf32(rb[3]));
        float4 b1 = make_float4(to_tf32(rb[4]), to_tf32(rb[5]), to_tf32(rb[6]), to_tf32(rb[7]));
        *(float4*)&Bs[buf][bn * BSTR + bk0]     = b0;
        *(float4*)&Bs[buf][bn * BSTR + bk0 + 8] = b1;
    };

    float acc[4][4][4] = {};

    // ldmatrix source lane mapping
    const int a_r    = (lane & 7) + ((lane >> 3) & 1) * 8;
    const int a_coff = (lane >> 4) * 4;
    const int b_r    = (lane & 7) + (lane >> 4) * 8;
    const int b_coff = ((lane >> 3) & 1) * 4;

    auto compute = [&](int buf){
        #pragma unroll
        for (int kk = 0; kk < GBK; kk += 8){
            uint32_t afr[4][4];
            #pragma unroll
            for (int mt = 0; mt < 4; mt++){
                uint32_t addr = (uint32_t)__cvta_generic_to_shared(
                    &As[buf][(warpM + mt*16 + a_r) * ASTR + kk + a_coff]);
                asm volatile("ldmatrix.sync.aligned.m8n8.x4.shared.b16 {%0,%1,%2,%3}, [%4];"
                    : "=r"(afr[mt][0]), "=r"(afr[mt][1]), "=r"(afr[mt][2]), "=r"(afr[mt][3])
                    : "r"(addr));
            }
            uint32_t bfr[2][4];
            #pragma unroll
            for (int np = 0; np < 2; np++){
                uint32_t addr = (uint32_t)__cvta_generic_to_shared(
                    &Bs[buf][(warpN + np*16 + b_r) * BSTR + kk + b_coff]);
                asm volatile("ldmatrix.sync.aligned.m8n8.x4.shared.b16 {%0,%1,%2,%3}, [%4];"
                    : "=r"(bfr[np][0]), "=r"(bfr[np][1]), "=r"(bfr[np][2]), "=r"(bfr[np][3])
                    : "r"(addr));
            }
            #pragma unroll
            for (int mt = 0; mt < 4; mt++)
                #pragma unroll
                for (int nt = 0; nt < 4; nt++){
                    uint32_t b0 = bfr[nt >> 1][(nt & 1) * 2];
                    uint32_t b1 = bfr[nt >> 1][(nt & 1) * 2 + 1];
                    asm volatile(
                        "mma.sync.aligned.m16n8k8.row.col.f32.tf32.tf32.f32 "
                        "{%0,%1,%2,%3},{%4,%5,%6,%7},{%8,%9},{%0,%1,%2,%3};"
                        : "+f"(acc[mt][nt][0]), "+f"(acc[mt][nt][1]),
                          "+f"(acc[mt][nt][2]), "+f"(acc[mt][nt][3])
                        : "r"(afr[mt][0]), "r"(afr[mt][1]), "r"(afr[mt][2]), "r"(afr[mt][3]),
                          "r"(b0), "r"(b1));
                }
        }
    };

    const int ntiles = K / GBK;
    ldg_tile(0);
    sts_tile(0);
    __syncthreads();
    for (int t = 0; t < ntiles; t++){
        if (t + 1 < ntiles) ldg_tile((t + 1) * GBK);
        compute(t & 1);
        if (t + 1 < ntiles) sts_tile((t + 1) & 1);
        __syncthreads();
    }

    // epilogue
    #pragma unroll
    for (int mt = 0; mt < 4; mt++){
        #pragma unroll
        for (int nt = 0; nt < 4; nt++){
            int rr = row0 + warpM + mt*16 + (lane >> 2);
            int cc = col0 + warpN + nt*8 + (lane & 3) * 2;
            #pragma unroll
            for (int half = 0; half < 2; half++){
                int r = rr + half * 8;
                float v0 = acc[mt][nt][half*2]     + bias[cc];
                float v1 = acc[mt][nt][half*2 + 1] + bias[cc + 1];
                if (resid){
                    const float2 rv = *(const float2*)&resid[(size_t)r * N + cc];
                    v0 += rv.x; v1 += rv.y;
                }
                if (do_gelu){
                    v0 = 0.5f * v0 * (1.f + erff(v0 * 0.70710678118f));
                    v1 = 0.5f * v1 * (1.f + erff(v1 * 0.70710678118f));
                }
                *(float2*)&out[(size_t)r * N + cc] = make_float2(v0, v1);
            }
        }
    }
}

// ---------------------------------------------------------------- Attention
#define ATTN_SMEM ((2*64*68 + 64*64 + 64*68) * 4)

__global__ void attn_kernel(const float* __restrict__ Q, const float* __restrict__ V,
                            const float* __restrict__ E, const float* __restrict__ gain,
                            const float* __restrict__ bias, float* __restrict__ out){
    extern __shared__ float sm[];
    float* Qt = sm;
    float* Et = sm + 64*68;
    float* Vs = sm + 2*64*68;
    float* Ps = sm + 2*64*68 + 64*64;
    const int tid = threadIdx.x;
    const int tx = tid & 15, ty = tid >> 4;
    const int bh = blockIdx.y, b = bh >> 4, h = bh & 15;
    const int t0 = blockIdx.x << 6;
    const int lr = tid >> 2, lc = (tid & 3) << 4;

    {
        const float* qp = Q + ((size_t)(b*Tt + t0 + lr)) * Cc + h*Dd + lc;
        #pragma unroll
        for (int q = 0; q < 4; q++){
            float4 v4 = *(const float4*)(qp + q*4);
            Qt[(lc+q*4+0)*68 + lr] = v4.x;
            Qt[(lc+q*4+1)*68 + lr] = v4.y;
            Qt[(lc+q*4+2)*68 + lr] = v4.z;
            Qt[(lc+q*4+3)*68 + lr] = v4.w;
        }
    }
    float gv[4], bv[4];
    #pragma unroll
    for (int i = 0; i < 4; i++){
        int t = t0 + (ty << 2) + i;
        gv[i] = gain[h*Tt + t];
        bv[i] = bias[h*Tt + t];
    }
    float acc[4][4] = {};
    float rsum[4] = {};

    for (int s0 = 0; s0 <= t0; s0 += 64){
        {
            const float* ep = E + ((size_t)(h*Tt + s0 + lr)) * Dd + lc;
            #pragma unroll
            for (int q = 0; q < 4; q++){
                float4 v4 = *(const float4*)(ep + q*4);
                Et[(lc+q*4+0)*68 + lr] = v4.x;
                Et[(lc+q*4+1)*68 + lr] = v4.y;
                Et[(lc+q*4+2)*68 + lr] = v4.z;
                Et[(lc+q*4+3)*68 + lr] = v4.w;
            }
            const float* vp = V + ((size_t)(b*Tt + s0 + lr)) * Cc + h*Dd + lc;
            #pragma unroll
            for (int q = 0; q < 4; q++)
                *(float4*)&Vs[lr*64 + lc + q*4] = *(const float4*)(vp + q*4);
        }
        __syncthreads();

        float dot[4][4] = {};
        #pragma unroll 8
        for (int d = 0; d < 64; d++){
            float4 qa = *(const float4*)&Qt[d*68 + (ty << 2)];
            float4 eb = *(const float4*)&Et[d*68 + (tx << 2)];
            float qf[4] = {qa.x, qa.y, qa.z, qa.w};
            float ef[4] = {eb.x, eb.y, eb.z, eb.w};
            #pragma unroll
            for (int i = 0; i < 4; i++)
                #pragma unroll
                for (int j = 0; j < 4; j++)
                    dot[i][j] = fmaf(qf[i], ef[j], dot[i][j]);
        }
        #pragma unroll
        for (int i = 0; i < 4; i++){
            int t = t0 + (ty << 2) + i;
            #pragma unroll
            for (int j = 0; j < 4; j++){
                int s = s0 + (tx << 2) + j;
                float p = 0.f;
                if (s <= t){
                    float I = fmaf(gv[i], dot[i][j], bv[i]);
                    if (I > 1.0000001f){
                        float rr = 1.0f / (0.002f - 0.02f * log1pf(-1.0f / I));
                        p = expf(rr * 0.125f);
                    } else {
                        p = 1.0f;
                    }
                }
                Ps[((ty<<2)+i)*68 + (tx<<2)+j] = p;
            }
        }
        __syncthreads();

        #pragma unroll 4
        for (int s = 0; s < 64; s++){
            float4 vvv = *(const float4*)&Vs[s*64 + (tx << 2)];
            float vf[4] = {vvv.x, vvv.y, vvv.z, vvv.w};
            #pragma unroll
            for (int i = 0; i < 4; i++){
                float pv = Ps[((ty<<2)+i)*68 + s];
                rsum[i] += pv;
                #pragma unroll
                for (int j = 0; j < 4; j++)
                    acc[i][j] = fmaf(pv, vf[j], acc[i][j]);
            }
        }
        __syncthreads();
    }

    #pragma unroll
    for (int i = 0; i < 4; i++){
        float inv = 1.0f / rsum[i];
        float4 o;
        o.x = acc[i][0]*inv; o.y = acc[i][1]*inv;
        o.z = acc[i][2]*inv; o.w = acc[i][3]*inv;
        int t = t0 + (ty << 2) + i;
        *(float4*)&out[((size_t)(b*Tt + t)) * Cc + h*Dd + (tx << 2)] = o;
    }
}

// ---------------------------------------------------------------- launch
extern "C" void kernel_launch(void* const* d_in, const int* in_sizes, int n_in,
                              void* d_out, int out_size){
    const float* x      = (const float*)d_in[0];
    const float* ln1_g  = (const float*)d_in[1];
    const float* ln1_b  = (const float*)d_in[2];
    const float* qkv_w  = (const float*)d_in[3];
    const float* qkv_b  = (const float*)d_in[4];
    const float* out_w  = (const float*)d_in[5];
    const float* out_b  = (const float*)d_in[6];
    const float* ln2_g  = (const float*)d_in[7];
    const float* ln2_b  = (const float*)d_in[8];
    const float* mlp_w1 = (const float*)d_in[9];
    const float* mlp_b1 = (const float*)d_in[10];
    const float* mlp_w2 = (const float*)d_in[11];
    const float* mlp_b2 = (const float*)d_in[12];
    const float* enc    = (const float*)d_in[13];
    const float* gain   = (const float*)d_in[14];
    const float* battn  = (const float*)d_in[15];
    float* outp = (float*)d_out;

    float *xn, *q, *v, *att, *x1, *hbuf;
    cudaGetSymbolAddress((void**)&xn,   g_xn);
    cudaGetSymbolAddress((void**)&q,    g_q);
    cudaGetSymbolAddress((void**)&v,    g_v);
    cudaGetSymbolAddress((void**)&att,  g_att);
    cudaGetSymbolAddress((void**)&x1,   g_x1);
    cudaGetSymbolAddress((void**)&hbuf, g_h);

    cudaFuncSetAttribute(attn_kernel, cudaFuncAttributeMaxDynamicSharedMemorySize, ATTN_SMEM);

    const int M = Bb * Tt;   // 4096

    // 1) LN1
    ln_kernel<<<M, 256>>>(x, ln1_g, ln1_b, xn);
    // 2) Q = xn @ qkv_w[:, 0:1024]   (K projection unused by reference)
    gemm_tc<<<dim3(Cc/GBN, M/GBM), 256>>>(xn, Cc, qkv_w,        3*Cc, qkv_b,        nullptr, q, Cc, Cc, 0);
    // 3) V = xn @ qkv_w[:, 2048:3072]
    gemm_tc<<<dim3(Cc/GBN, M/GBM), 256>>>(xn, Cc, qkv_w + 2*Cc, 3*Cc, qkv_b + 2*Cc, nullptr, v, Cc, Cc, 0);
    // 4) attention
    attn_kernel<<<dim3(Tt/64, Bb*Hh), 256, ATTN_SMEM>>>(q, v, enc, gain, battn, att);
    // 5) x1 = x + att @ out_w + out_b
    gemm_tc<<<dim3(Cc/GBN, M/GBM), 256>>>(att, Cc, out_w, Cc, out_b, x, x1, Cc, Cc, 0);
    // 6) LN2
    ln_kernel<<<M, 256>>>(x1, ln2_g, ln2_b, xn);
    // 7) h = gelu(xn @ mlp_w1 + b1)
    gemm_tc<<<dim3(4*Cc/GBN, M/GBM), 256>>>(xn, Cc, mlp_w1, 4*Cc, mlp_b1, nullptr, hbuf, 4*Cc, Cc, 1);
    // 8) out = x1 + h @ mlp_w2 + b2
    gemm_tc<<<dim3(Cc/GBN, M/GBM), 256>>>(hbuf, 4*Cc, mlp_w2, Cc, mlp_b2, x1, outp, Cc, 4*Cc, 0);
}

// round 3
// speedup vs baseline: 2.8237x; 1.4091x over previous
#include <cuda_runtime.h>
#include <math.h>
#include <stdint.h>

#define Bb 2
#define Tt 2048
#define Cc 1024
#define Hh 16
#define Dd 64

__device__ float g_xn [Bb*Tt*Cc];
__device__ float g_q  [Bb*Tt*Cc];
__device__ float g_v  [Bb*Tt*Cc];
__device__ float g_att[Bb*Tt*Cc];
__device__ float g_x1 [Bb*Tt*Cc];
__device__ float g_h  [Bb*Tt*4*Cc];

// ---------------------------------------------------------------- block reduce
__device__ __forceinline__ float block_sum(float v, volatile float* red){
    #pragma unroll
    for (int o = 16; o; o >>= 1) v += __shfl_xor_sync(0xffffffffu, v, o);
    int lane = threadIdx.x & 31, w = threadIdx.x >> 5;
    if (lane == 0) red[w] = v;
    __syncthreads();
    if (w == 0){
        v = (lane < 8) ? red[lane] : 0.f;
        #pragma unroll
        for (int o = 4; o; o >>= 1) v += __shfl_xor_sync(0xffffffffu, v, o);
    }
    return v;
}

// ---------------------------------------------------------------- LayerNorm
__global__ void ln_kernel(const float* __restrict__ x, const float* __restrict__ g,
                          const float* __restrict__ b, float* __restrict__ out){
    __shared__ float red[8];
    __shared__ float s_mu, s_rs;
    int row = blockIdx.x, tid = threadIdx.x;
    const float4 v = ((const float4*)(x + (size_t)row * Cc))[tid];
    float s = v.x + v.y + v.z + v.w;
    s = block_sum(s, red);
    if (tid == 0) s_mu = s * (1.0f / Cc);
    __syncthreads();
    float mu = s_mu;
    float dx = v.x - mu, dy = v.y - mu, dz = v.z - mu, dw = v.w - mu;
    float sq = dx*dx + dy*dy + dz*dz + dw*dw;
    sq = block_sum(sq, red);
    if (tid == 0) s_rs = rsqrtf(sq * (1.0f / Cc) + 1e-5f);
    __syncthreads();
    float rs = s_rs;
    float4 gg = ((const float4*)g)[tid], bb = ((const float4*)b)[tid];
    float4 o;
    o.x = dx * rs * gg.x + bb.x;
    o.y = dy * rs * gg.y + bb.y;
    o.z = dz * rs * gg.z + bb.z;
    o.w = dw * rs * gg.w + bb.w;
    ((float4*)(out + (size_t)row * Cc))[tid] = o;
}

__device__ __forceinline__ float to_tf32(float x){
    float r; asm("cvt.rna.tf32.f32 %0, %1;" : "=f"(r) : "f"(x)); return r;
}

// ---------------------------------------------------------------- tf32 tensor GEMM
#define GBM 128
#define GBN 128
#define GBK 16
#define ASTR 20
#define BSTR 20

__global__ __launch_bounds__(256) void gemm_tc(
        const float* __restrict__ A, int lda,
        const float* __restrict__ W, int ldw,
        const float* __restrict__ bias,
        const float* __restrict__ resid,
        float* __restrict__ out,
        int N, int K, int do_gelu){
    __shared__ float As[2][GBM*ASTR];
    __shared__ float Bs[2][GBN*BSTR];
    const int tid = threadIdx.x;
    const int lane = tid & 31, w = tid >> 5;
    const int warpM = (w & 1) * 64, warpN = (w >> 1) * 32;
    const int row0 = blockIdx.y * GBM, col0 = blockIdx.x * GBN;

    const int am = tid >> 1, ak = (tid & 1) * 8;
    const float* Ap = A + (size_t)(row0 + am) * lda + ak;
    const int bn = (w & 3) * 32 + lane;
    const int bk0 = (w >> 2) * 4;
    const float* Bp = W + (size_t)bk0 * ldw + col0 + bn;

    float4 ra0, ra1;
    float rb[8];

    auto ldg_tile = [&](int kt){
        ra0 = *(const float4*)(Ap + kt);
        ra1 = *(const float4*)(Ap + kt + 4);
        #pragma unroll
        for (int j = 0; j < 4; j++){
            rb[j]     = Bp[(size_t)(kt + j) * ldw];
            rb[4 + j] = Bp[(size_t)(kt + 8 + j) * ldw];
        }
    };
    auto sts_tile = [&](int buf){
        float4 c0 = make_float4(to_tf32(ra0.x), to_tf32(ra0.y), to_tf32(ra0.z), to_tf32(ra0.w));
        float4 c1 = make_float4(to_tf32(ra1.x), to_tf32(ra1.y), to_tf32(ra1.z), to_tf32(ra1.w));
        *(float4*)&As[buf][am * ASTR + ak]     = c0;
        *(float4*)&As[buf][am * ASTR + ak + 4] = c1;
        float4 b0 = make_float4(to_tf32(rb[0]), to_tf32(rb[1]), to_tf32(rb[2]), to_tf32(rb[3]));
        float4 b1 = make_float4(to_tf32(rb[4]), to_tf32(rb[5]), to_tf32(rb[6]), to_tf32(rb[7]));
        *(float4*)&Bs[buf][bn * BSTR + bk0]     = b0;
        *(float4*)&Bs[buf][bn * BSTR + bk0 + 8] = b1;
    };

    float acc[4][4][4] = {};

    const int a_r    = (lane & 7) + ((lane >> 3) & 1) * 8;
    const int a_coff = (lane >> 4) * 4;
    const int b_r    = (lane & 7) + (lane >> 4) * 8;
    const int b_coff = ((lane >> 3) & 1) * 4;

    auto compute = [&](int buf){
        #pragma unroll
        for (int kk = 0; kk < GBK; kk += 8){
            uint32_t afr[4][4];
            #pragma unroll
            for (int mt = 0; mt < 4; mt++){
                uint32_t addr = (uint32_t)__cvta_generic_to_shared(
                    &As[buf][(warpM + mt*16 + a_r) * ASTR + kk + a_coff]);
                asm volatile("ldmatrix.sync.aligned.m8n8.x4.shared.b16 {%0,%1,%2,%3}, [%4];"
                    : "=r"(afr[mt][0]), "=r"(afr[mt][1]), "=r"(afr[mt][2]), "=r"(afr[mt][3])
                    : "r"(addr));
            }
            uint32_t bfr[2][4];
            #pragma unroll
            for (int np = 0; np < 2; np++){
                uint32_t addr = (uint32_t)__cvta_generic_to_shared(
                    &Bs[buf][(warpN + np*16 + b_r) * BSTR + kk + b_coff]);
                asm volatile("ldmatrix.sync.aligned.m8n8.x4.shared.b16 {%0,%1,%2,%3}, [%4];"
                    : "=r"(bfr[np][0]), "=r"(bfr[np][1]), "=r"(bfr[np][2]), "=r"(bfr[np][3])
                    : "r"(addr));
            }
            #pragma unroll
            for (int mt = 0; mt < 4; mt++)
                #pragma unroll
                for (int nt = 0; nt < 4; nt++){
                    uint32_t b0 = bfr[nt >> 1][(nt & 1) * 2];
                    uint32_t b1 = bfr[nt >> 1][(nt & 1) * 2 + 1];
                    asm volatile(
                        "mma.sync.aligned.m16n8k8.row.col.f32.tf32.tf32.f32 "
                        "{%0,%1,%2,%3},{%4,%5,%6,%7},{%8,%9},{%0,%1,%2,%3};"
                        : "+f"(acc[mt][nt][0]), "+f"(acc[mt][nt][1]),
                          "+f"(acc[mt][nt][2]), "+f"(acc[mt][nt][3])
                        : "r"(afr[mt][0]), "r"(afr[mt][1]), "r"(afr[mt][2]), "r"(afr[mt][3]),
                          "r"(b0), "r"(b1));
                }
        }
    };

    const int ntiles = K / GBK;
    ldg_tile(0);
    sts_tile(0);
    __syncthreads();
    for (int t = 0; t < ntiles; t++){
        if (t + 1 < ntiles) ldg_tile((t + 1) * GBK);
        compute(t & 1);
        if (t + 1 < ntiles) sts_tile((t + 1) & 1);
        __syncthreads();
    }

    #pragma unroll
    for (int mt = 0; mt < 4; mt++){
        #pragma unroll
        for (int nt = 0; nt < 4; nt++){
            int rr = row0 + warpM + mt*16 + (lane >> 2);
            int cc = col0 + warpN + nt*8 + (lane & 3) * 2;
            #pragma unroll
            for (int half = 0; half < 2; half++){
                int r = rr + half * 8;
                float v0 = acc[mt][nt][half*2]     + bias[cc];
                float v1 = acc[mt][nt][half*2 + 1] + bias[cc + 1];
                if (resid){
                    const float2 rv = *(const float2*)&resid[(size_t)r * N + cc];
                    v0 += rv.x; v1 += rv.y;
                }
                if (do_gelu){
                    v0 = 0.5f * v0 * (1.f + erff(v0 * 0.70710678118f));
                    v1 = 0.5f * v1 * (1.f + erff(v1 * 0.70710678118f));
                }
                *(float2*)&out[(size_t)r * N + cc] = make_float2(v0, v1);
            }
        }
    }
}

// ---------------------------------------------------------------- Attention (tensor core)
// M=128 queries per block (8 warps x 16 rows), 64-key s-tiles.
// smem: Es[64][68] (B-op for QE), Vt[64][68] (V^T, B-op for PV),
//       Ps[128][68] (P rows, A-op for PV; also Q staging at start).
#define ESTR 68
#define ATTN_SMEM ((64*ESTR + 64*ESTR + 128*ESTR) * 4)

__device__ __forceinline__ float lif_p(float I){
    // p = exp(rate/8); rate = 1/(0.002 - 0.02*ln(1 - 1/I)) for I>1 else 0
    if (I > 1.0000001f){
        float u = __fdividef(1.0f, I);
        float d = fmaf(-0.02f, __logf(1.0f - u), 0.002f);
        return __expf(__fdividef(0.125f, d));
    }
    return 1.0f;   // exp(0)
}

__global__ __launch_bounds__(256) void attn_tc(
        const float* __restrict__ Q, const float* __restrict__ V,
        const float* __restrict__ E, const float* __restrict__ gain,
        const float* __restrict__ bias, float* __restrict__ out){
    extern __shared__ float sm[];
    float* Es = sm;                      // 64*68
    float* Vt = sm + 64*ESTR;            // 64*68
    float* Ps = sm + 2*64*ESTR;          // 128*68 (Q staging, then P)

    const int tid = threadIdx.x;
    const int lane = tid & 31, w = tid >> 5;
    const int bh = blockIdx.y, b = bh >> 4, h = bh & 15;
    const int t0 = blockIdx.x << 7;      // 128 queries
    const int rowbase = w << 4;          // warp's 16 rows

    const int a_r    = (lane & 7) + ((lane >> 3) & 1) * 8;
    const int a_coff = (lane >> 4) * 4;
    const int b_r    = (lane & 7) + (lane >> 4) * 8;
    const int b_coff = ((lane >> 3) & 1) * 4;

    // ---- stage Q tile into Ps region: [m][k], tf32
    {
        const int qr = tid >> 1, qc = (tid & 1) * 32;
        const float* qp = Q + ((size_t)(b*Tt + t0 + qr)) * Cc + h*Dd + qc;
        #pragma unroll
        for (int i = 0; i < 8; i++){
            float4 v4 = *(const float4*)(qp + i*4);
            *(float4*)&Ps[qr*ESTR + qc + i*4] = make_float4(
                to_tf32(v4.x), to_tf32(v4.y), to_tf32(v4.z), to_tf32(v4.w));
        }
    }
    __syncthreads();

    // ---- Q fragments (persistent): 8 k-steps x 4 regs
    uint32_t qa[8][4];
    #pragma unroll
    for (int kk = 0; kk < 8; kk++){
        uint32_t addr = (uint32_t)__cvta_generic_to_shared(
            &Ps[(rowbase + a_r) * ESTR + kk*8 + a_coff]);
        asm volatile("ldmatrix.sync.aligned.m8n8.x4.shared.b16 {%0,%1,%2,%3}, [%4];"
            : "=r"(qa[kk][0]), "=r"(qa[kk][1]), "=r"(qa[kk][2]), "=r"(qa[kk][3])
            : "r"(addr));
    }

    // per-thread row info (rows r and r+8 of warp tile)
    const int r = lane >> 2;
    const int cq = (lane & 3) << 1;
    const int tA = t0 + rowbase + r;
    const int tB = tA + 8;
    const float gA = gain[h*Tt + tA], bA = bias[h*Tt + tA];
    const float gB = gain[h*Tt + tB], bB = bias[h*Tt + tB];
    const int twmax = t0 + rowbase + 15;

    float oacc[8][4] = {};
    float psumA = 0.f, psumB = 0.f;

    for (int s0 = 0; s0 < t0 + 128; s0 += 64){
        __syncthreads();   // protect Es/Vt from previous iteration's readers
        // ---- stage E [s][d] and V^T [d][s]
        {
            const int lr = tid >> 2, cg = (tid & 3) * 16;
            const float* ep = E + ((size_t)(h*Tt + s0 + lr)) * Dd + cg;
            #pragma unroll
            for (int j = 0; j < 4; j++){
                float4 v4 = *(const float4*)(ep + j*4);
                *(float4*)&Es[lr*ESTR + cg + j*4] = make_float4(
                    to_tf32(v4.x), to_tf32(v4.y), to_tf32(v4.z), to_tf32(v4.w));
            }
            const float* vp = V + ((size_t)(b*Tt + s0 + lr)) * Cc + h*Dd + cg;
            #pragma unroll
            for (int j = 0; j < 4; j++){
                float4 v4 = *(const float4*)(vp + j*4);
                Vt[(cg+j*4+0)*ESTR + lr] = to_tf32(v4.x);
                Vt[(cg+j*4+1)*ESTR + lr] = to_tf32(v4.y);
                Vt[(cg+j*4+2)*ESTR + lr] = to_tf32(v4.z);
                Vt[(cg+j*4+3)*ESTR + lr] = to_tf32(v4.w);
            }
        }
        __syncthreads();

        if (s0 > twmax) continue;   // whole warp masked for this s-tile

        // ---- MMA1: S[16x64] = Q . E^T
        float sacc[8][4] = {};
        #pragma unroll
        for (int kk = 0; kk < 8; kk++){
            uint32_t bfr[4][4];
            #pragma unroll
            for (int np = 0; np < 4; np++){
                uint32_t addr = (uint32_t)__cvta_generic_to_shared(
                    &Es[(np*16 + b_r) * ESTR + kk*8 + b_coff]);
                asm volatile("ldmatrix.sync.aligned.m8n8.x4.shared.b16 {%0,%1,%2,%3}, [%4];"
                    : "=r"(bfr[np][0]), "=r"(bfr[np][1]), "=r"(bfr[np][2]), "=r"(bfr[np][3])
                    : "r"(addr));
            }
            #pragma unroll
            for (int nt = 0; nt < 8; nt++){
                uint32_t b0 = bfr[nt >> 1][(nt & 1) * 2];
                uint32_t b1 = bfr[nt >> 1][(nt & 1) * 2 + 1];
                asm volatile(
                    "mma.sync.aligned.m16n8k8.row.col.f32.tf32.tf32.f32 "
                    "{%0,%1,%2,%3},{%4,%5,%6,%7},{%8,%9},{%0,%1,%2,%3};"
                    : "+f"(sacc[nt][0]), "+f"(sacc[nt][1]),
                      "+f"(sacc[nt][2]), "+f"(sacc[nt][3])
                    : "r"(qa[kk][0]), "r"(qa[kk][1]), "r"(qa[kk][2]), "r"(qa[kk][3]),
                      "r"(b0), "r"(b1));
            }
        }

        // ---- elementwise LIF + causal mask -> Ps (own warp rows only)
        #pragma unroll
        for (int nt = 0; nt < 8; nt++){
            int sb = s0 + nt*8 + cq;
            float p00 = lif_p(fmaf(gA, sacc[nt][0], bA)); if (sb     > tA) p00 = 0.f;
            float p01 = lif_p(fmaf(gA, sacc[nt][1], bA)); if (sb + 1 > tA) p01 = 0.f;
            float p10 = lif_p(fmaf(gB, sacc[nt][2], bB)); if (sb     > tB) p10 = 0.f;
            float p11 = lif_p(fmaf(gB, sacc[nt][3], bB)); if (sb + 1 > tB) p11 = 0.f;
            psumA += p00 + p01;
            psumB += p10 + p11;
            *(float2*)&Ps[(rowbase + r    )*ESTR + nt*8 + cq] = make_float2(to_tf32(p00), to_tf32(p01));
            *(float2*)&Ps[(rowbase + r + 8)*ESTR + nt*8 + cq] = make_float2(to_tf32(p10), to_tf32(p11));
        }
        __syncwarp();

        // ---- MMA2: O += P . V^T(d-major)
        #pragma unroll
        for (int kk = 0; kk < 8; kk++){
            uint32_t afr[4];
            {
                uint32_t addr = (uint32_t)__cvta_generic_to_shared(
                    &Ps[(rowbase + a_r) * ESTR + kk*8 + a_coff]);
                asm volatile("ldmatrix.sync.aligned.m8n8.x4.shared.b16 {%0,%1,%2,%3}, [%4];"
                    : "=r"(afr[0]), "=r"(afr[1]), "=r"(afr[2]), "=r"(afr[3])
                    : "r"(addr));
            }
            uint32_t bfr[4][4];
            #pragma unroll
            for (int np = 0; np < 4; np++){
                uint32_t addr = (uint32_t)__cvta_generic_to_shared(
                    &Vt[(np*16 + b_r) * ESTR + kk*8 + b_coff]);
                asm volatile("ldmatrix.sync.aligned.m8n8.x4.shared.b16 {%0,%1,%2,%3}, [%4];"
                    : "=r"(bfr[np][0]), "=r"(bfr[np][1]), "=r"(bfr[np][2]), "=r"(bfr[np][3])
                    : "r"(addr));
            }
            #pragma unroll
            for (int nt = 0; nt < 8; nt++){
                uint32_t b0 = bfr[nt >> 1][(nt & 1) * 2];
                uint32_t b1 = bfr[nt >> 1][(nt & 1) * 2 + 1];
                asm volatile(
                    "mma.sync.aligned.m16n8k8.row.col.f32.tf32.tf32.f32 "
                    "{%0,%1,%2,%3},{%4,%5,%6,%7},{%8,%9},{%0,%1,%2,%3};"
                    : "+f"(oacc[nt][0]), "+f"(oacc[nt][1]),
                      "+f"(oacc[nt][2]), "+f"(oacc[nt][3])
                    : "r"(afr[0]), "r"(afr[1]), "r"(afr[2]), "r"(afr[3]),
                      "r"(b0), "r"(b1));
            }
        }
    }

    // ---- normalize + store
    psumA += __shfl_xor_sync(0xffffffffu, psumA, 1);
    psumA += __shfl_xor_sync(0xffffffffu, psumA, 2);
    psumB += __shfl_xor_sync(0xffffffffu, psumB, 1);
    psumB += __shfl_xor_sync(0xffffffffu, psumB, 2);
    float invA = 1.0f / psumA;
    float invB = 1.0f / psumB;

    float* opA = out + ((size_t)(b*Tt + tA)) * Cc + h*Dd;
    float* opB = out + ((size_t)(b*Tt + tB)) * Cc + h*Dd;
    #pragma unroll
    for (int nt = 0; nt < 8; nt++){
        int d = nt*8 + cq;
        *(float2*)&opA[d] = make_float2(oacc[nt][0]*invA, oacc[nt][1]*invA);
        *(float2*)&opB[d] = make_float2(oacc[nt][2]*invB, oacc[nt][3]*invB);
    }
}

// ---------------------------------------------------------------- launch
extern "C" void kernel_launch(void* const* d_in, const int* in_sizes, int n_in,
                              void* d_out, int out_size){
    const float* x      = (const float*)d_in[0];
    const float* ln1_g  = (const float*)d_in[1];
    const float* ln1_b  = (const float*)d_in[2];
    const float* qkv_w  = (const float*)d_in[3];
    const float* qkv_b  = (const float*)d_in[4];
    const float* out_w  = (const float*)d_in[5];
    const float* out_b  = (const float*)d_in[6];
    const float* ln2_g  = (const float*)d_in[7];
    const float* ln2_b  = (const float*)d_in[8];
    const float* mlp_w1 = (const float*)d_in[9];
    const float* mlp_b1 = (const float*)d_in[10];
    const float* mlp_w2 = (const float*)d_in[11];
    const float* mlp_b2 = (const float*)d_in[12];
    const float* enc    = (const float*)d_in[13];
    const float* gain   = (const float*)d_in[14];
    const float* battn  = (const float*)d_in[15];
    float* outp = (float*)d_out;

    float *xn, *q, *v, *att, *x1, *hbuf;
    cudaGetSymbolAddress((void**)&xn,   g_xn);
    cudaGetSymbolAddress((void**)&q,    g_q);
    cudaGetSymbolAddress((void**)&v,    g_v);
    cudaGetSymbolAddress((void**)&att,  g_att);
    cudaGetSymbolAddress((void**)&x1,   g_x1);
    cudaGetSymbolAddress((void**)&hbuf, g_h);

    cudaFuncSetAttribute(attn_tc, cudaFuncAttributeMaxDynamicSharedMemorySize, ATTN_SMEM);

    const int M = Bb * Tt;   // 4096

    ln_kernel<<<M, 256>>>(x, ln1_g, ln1_b, xn);
    gemm_tc<<<dim3(Cc/GBN, M/GBM), 256>>>(xn, Cc, qkv_w,        3*Cc, qkv_b,        nullptr, q, Cc, Cc, 0);
    gemm_tc<<<dim3(Cc/GBN, M/GBM), 256>>>(xn, Cc, qkv_w + 2*Cc, 3*Cc, qkv_b + 2*Cc, nullptr, v, Cc, Cc, 0);
    attn_tc<<<dim3(Tt/128, Bb*Hh), 256, ATTN_SMEM>>>(q, v, enc, gain, battn, att);
    gemm_tc<<<dim3(Cc/GBN, M/GBM), 256>>>(att, Cc, out_w, Cc, out_b, x, x1, Cc, Cc, 0);
    ln_kernel<<<M, 256>>>(x1, ln2_g, ln2_b, xn);
    gemm_tc<<<dim3(4*Cc/GBN, M/GBM), 256>>>(xn, Cc, mlp_w1, 4*Cc, mlp_b1, nullptr, hbuf, 4*Cc, Cc, 1);
    gemm_tc<<<dim3(Cc/GBN, M/GBM), 256>>>(hbuf, 4*Cc, mlp_w2, Cc, mlp_b2, x1, outp, Cc, 4*Cc, 0);
}

// round 5
// speedup vs baseline: 3.0777x; 1.0900x over previous
#include <cuda_runtime.h>
#include <cuda_fp16.h>
#include <math.h>
#include <stdint.h>

#define Bb 2
#define Tt 2048
#define Cc 1024
#define Hh 16
#define Dd 64

__device__ float  g_xn [Bb*Tt*Cc];
__device__ float  g_qv [Bb*Tt*2*Cc];     // fused Q|V, row stride 2048
__device__ float  g_att[Bb*Tt*Cc];
__device__ float  g_x1 [Bb*Tt*Cc];
__device__ float  g_h  [Bb*Tt*4*Cc];
__device__ __half g_wqv[2*Cc*Cc];        // [N=2048][K=1024]
__device__ __half g_wo [Cc*Cc];
__device__ __half g_w1 [4*Cc*Cc];
__device__ __half g_w2 [Cc*4*Cc];
__device__ float  g_qvb[2*Cc];

__device__ __forceinline__ float to_tf32(float x){
    float r; asm("cvt.rna.tf32.f32 %0, %1;" : "=f"(r) : "f"(x)); return r;
}

// ======================== prep kernels ========================
__global__ void pack_bias(const float* __restrict__ qkv_b, float* __restrict__ qvb){
    int i = blockIdx.x * 256 + threadIdx.x;          // 2048 threads
    qvb[i] = (i < Cc) ? qkv_b[i] : qkv_b[i + Cc];    // skip K slice
}

// Wt[N,K] = half(W[K,N]); grid(N/32, K/32), block(32,8)
__global__ void transpose_h(const float* __restrict__ W, int ldw,
                            __half* __restrict__ Wt, int K){
    __shared__ float t[32][33];
    int n0 = blockIdx.x * 32, k0 = blockIdx.y * 32;
    int tx = threadIdx.x, ty = threadIdx.y;
    #pragma unroll
    for (int i = 0; i < 4; i++)
        t[ty + i*8][tx] = W[(size_t)(k0 + ty + i*8) * ldw + n0 + tx];
    __syncthreads();
    #pragma unroll
    for (int i = 0; i < 4; i++)
        Wt[(size_t)(n0 + ty + i*8) * K + k0 + tx] = __float2half_rn(t[tx][ty + i*8]);
}

// ======================== block reduce / LayerNorm ========================
__device__ __forceinline__ float block_sum(float v, volatile float* red){
    #pragma unroll
    for (int o = 16; o; o >>= 1) v += __shfl_xor_sync(0xffffffffu, v, o);
    int lane = threadIdx.x & 31, w = threadIdx.x >> 5;
    if (lane == 0) red[w] = v;
    __syncthreads();
    if (w == 0){
        v = (lane < 8) ? red[lane] : 0.f;
        #pragma unroll
        for (int o = 4; o; o >>= 1) v += __shfl_xor_sync(0xffffffffu, v, o);
    }
    return v;
}

__global__ void ln_kernel(const float* __restrict__ x, const float* __restrict__ g,
                          const float* __restrict__ b, float* __restrict__ out){
    __shared__ float red[8];
    __shared__ float s_mu, s_rs;
    int row = blockIdx.x, tid = threadIdx.x;
    const float4 v = ((const float4*)(x + (size_t)row * Cc))[tid];
    float s = v.x + v.y + v.z + v.w;
    s = block_sum(s, red);
    if (tid == 0) s_mu = s * (1.0f / Cc);
    __syncthreads();
    float mu = s_mu;
    float dx = v.x - mu, dy = v.y - mu, dz = v.z - mu, dw = v.w - mu;
    float sq = dx*dx + dy*dy + dz*dz + dw*dw;
    sq = block_sum(sq, red);
    if (tid == 0) s_rs = rsqrtf(sq * (1.0f / Cc) + 1e-5f);
    __syncthreads();
    float rs = s_rs;
    float4 gg = ((const float4*)g)[tid], bb = ((const float4*)b)[tid];
    float4 o;
    o.x = dx * rs * gg.x + bb.x;
    o.y = dy * rs * gg.y + bb.y;
    o.z = dz * rs * gg.z + bb.z;
    o.w = dw * rs * gg.w + bb.w;
    ((float4*)(out + (size_t)row * Cc))[tid] = o;
}

// ======================== fp16 tensor GEMM ========================
// out[M,N] = A[M,K](f32) @ Bt[N,K](f16)^T + bias (+resid)(+gelu)
// BM=BN=128, BK=32, 256 thr (8 warps 2m x 4n, warp tile 64x32), m16n8k16.
#define HSTR 40   // half stride per row: 5*row mod 8 permutation, conflict-free ldmatrix

__global__ __launch_bounds__(256) void gemm_h(
        const float* __restrict__ A,
        const __half* __restrict__ Bt,
        const float* __restrict__ bias,
        const float* __restrict__ resid,
        float* __restrict__ out,
        int N, int K, int do_gelu){
    __shared__ __half As[2][128*HSTR];
    __shared__ __half Bs[2][128*HSTR];
    const int tid = threadIdx.x;
    const int lane = tid & 31, w = tid >> 5;
    const int warpM = (w & 1) * 64, warpN = (w >> 1) * 32;
    const int row0 = blockIdx.y * 128, col0 = blockIdx.x * 128;

    const int sr = tid >> 1;             // staged row (m for A, n for B)
    const int kh = (tid & 1) * 16;       // k offset (halves)
    const float* Ap = A + (size_t)(row0 + sr) * K + kh;
    const __half* Bp = Bt + (size_t)(col0 + sr) * K + kh;

    float4 ra[4];
    uint4  rb[2];

    auto ldg_tile = [&](int kt){
        ra[0] = *(const float4*)(Ap + kt);
        ra[1] = *(const float4*)(Ap + kt + 4);
        ra[2] = *(const float4*)(Ap + kt + 8);
        ra[3] = *(const float4*)(Ap + kt + 12);
        rb[0] = *(const uint4*)(Bp + kt);
        rb[1] = *(const uint4*)(Bp + kt + 8);
    };
    auto sts_tile = [&](int buf){
        uint32_t h[8];
        #pragma unroll
        for (int i = 0; i < 4; i++){
            __half2 lo = __floats2half2_rn(ra[i].x, ra[i].y);
            __half2 hi = __floats2half2_rn(ra[i].z, ra[i].w);
            h[i*2]   = *(uint32_t*)&lo;
            h[i*2+1] = *(uint32_t*)&hi;
        }
        *(uint4*)&As[buf][sr*HSTR + kh]     = make_uint4(h[0], h[1], h[2], h[3]);
        *(uint4*)&As[buf][sr*HSTR + kh + 8] = make_uint4(h[4], h[5], h[6], h[7]);
        *(uint4*)&Bs[buf][sr*HSTR + kh]     = rb[0];
        *(uint4*)&Bs[buf][sr*HSTR + kh + 8] = rb[1];
    };

    float acc[4][4][4] = {};

    // ldmatrix lane-address components
    const int a_row  = lane & 15;                 // rows 0-15
    const int a_col  = (lane >> 4) * 8;           // col halves 0/8
    const int b_row  = (lane & 7) + ((lane >> 4) << 3);   // n rows: m0/m1 n0-7, m2/m3 n8-15
    const int b_col  = ((lane >> 3) & 1) * 8;             // m0,m2 k0-7 ; m1,m3 k8-15

    auto compute = [&](int buf){
        #pragma unroll
        for (int kk = 0; kk < 2; kk++){
            uint32_t afr[4][4];
            #pragma unroll
            for (int mt = 0; mt < 4; mt++){
                uint32_t addr = (uint32_t)__cvta_generic_to_shared(
                    &As[buf][(warpM + mt*16 + a_row) * HSTR + kk*16 + a_col]);
                asm volatile("ldmatrix.sync.aligned.m8n8.x4.shared.b16 {%0,%1,%2,%3}, [%4];"
                    : "=r"(afr[mt][0]), "=r"(afr[mt][1]), "=r"(afr[mt][2]), "=r"(afr[mt][3])
                    : "r"(addr));
            }
            uint32_t bfr[2][4];
            #pragma unroll
            for (int ng = 0; ng < 2; ng++){
                uint32_t addr = (uint32_t)__cvta_generic_to_shared(
                    &Bs[buf][(warpN + ng*16 + b_row) * HSTR + kk*16 + b_col]);
                asm volatile("ldmatrix.sync.aligned.m8n8.x4.shared.b16 {%0,%1,%2,%3}, [%4];"
                    : "=r"(bfr[ng][0]), "=r"(bfr[ng][1]), "=r"(bfr[ng][2]), "=r"(bfr[ng][3])
                    : "r"(addr));
            }
            #pragma unroll
            for (int mt = 0; mt < 4; mt++)
                #pragma unroll
                for (int nt = 0; nt < 4; nt++){
                    uint32_t b0 = bfr[nt >> 1][(nt & 1) * 2];
                    uint32_t b1 = bfr[nt >> 1][(nt & 1) * 2 + 1];
                    asm volatile(
                        "mma.sync.aligned.m16n8k16.row.col.f32.f16.f16.f32 "
                        "{%0,%1,%2,%3},{%4,%5,%6,%7},{%8,%9},{%0,%1,%2,%3};"
                        : "+f"(acc[mt][nt][0]), "+f"(acc[mt][nt][1]),
                          "+f"(acc[mt][nt][2]), "+f"(acc[mt][nt][3])
                        : "r"(afr[mt][0]), "r"(afr[mt][1]), "r"(afr[mt][2]), "r"(afr[mt][3]),
                          "r"(b0), "r"(b1));
                }
        }
    };

    const int ntiles = K / 32;
    ldg_tile(0);
    sts_tile(0);
    __syncthreads();
    for (int t = 0; t < ntiles; t++){
        if (t + 1 < ntiles) ldg_tile((t + 1) * 32);
        compute(t & 1);
        if (t + 1 < ntiles) sts_tile((t + 1) & 1);
        __syncthreads();
    }

    #pragma unroll
    for (int mt = 0; mt < 4; mt++){
        #pragma unroll
        for (int nt = 0; nt < 4; nt++){
            int rr = row0 + warpM + mt*16 + (lane >> 2);
            int cc = col0 + warpN + nt*8 + (lane & 3) * 2;
            #pragma unroll
            for (int half = 0; half < 2; half++){
                int r = rr + half * 8;
                float v0 = acc[mt][nt][half*2]     + bias[cc];
                float v1 = acc[mt][nt][half*2 + 1] + bias[cc + 1];
                if (resid){
                    const float2 rv = *(const float2*)&resid[(size_t)r * N + cc];
                    v0 += rv.x; v1 += rv.y;
                }
                if (do_gelu){
                    v0 = 0.5f * v0 * (1.f + erff(v0 * 0.70710678118f));
                    v1 = 0.5f * v1 * (1.f + erff(v1 * 0.70710678118f));
                }
                *(float2*)&out[(size_t)r * N + cc] = make_float2(v0, v1);
            }
        }
    }
}

// ======================== Attention (mma.sync tf32) ========================
#define ESTR 68
#define QVLD (2*Cc)
#define ATTN_SMEM ((64*ESTR + 64*ESTR + 128*ESTR) * 4)

__device__ __forceinline__ float lif_p(float I){
    if (I > 1.0000001f){
        float u = __fdividef(1.0f, I);
        float d = fmaf(-0.02f, __logf(1.0f - u), 0.002f);
        return __expf(__fdividef(0.125f, d));
    }
    return 1.0f;
}

__global__ __launch_bounds__(256) void attn_tc(
        const float* __restrict__ Q, const float* __restrict__ V,
        const float* __restrict__ E, const float* __restrict__ gain,
        const float* __restrict__ bias, float* __restrict__ out){
    extern __shared__ float sm[];
    float* Es = sm;
    float* Vt = sm + 64*ESTR;
    float* Ps = sm + 2*64*ESTR;

    const int tid = threadIdx.x;
    const int lane = tid & 31, w = tid >> 5;
    const int bh = blockIdx.y, b = bh >> 4, h = bh & 15;
    const int t0 = (gridDim.x - 1 - blockIdx.x) << 7;   // heavy blocks first
    const int rowbase = w << 4;

    const int a_r    = (lane & 7) + ((lane >> 3) & 1) * 8;
    const int a_coff = (lane >> 4) * 4;
    const int b_r    = (lane & 7) + (lane >> 4) * 8;
    const int b_coff = ((lane >> 3) & 1) * 4;

    {
        const int qr = tid >> 1, qc = (tid & 1) * 32;
        const float* qp = Q + ((size_t)(b*Tt + t0 + qr)) * QVLD + h*Dd + qc;
        #pragma unroll
        for (int i = 0; i < 8; i++){
            float4 v4 = *(const float4*)(qp + i*4);
            *(float4*)&Ps[qr*ESTR + qc + i*4] = make_float4(
                to_tf32(v4.x), to_tf32(v4.y), to_tf32(v4.z), to_tf32(v4.w));
        }
    }
    __syncthreads();

    uint32_t qa[8][4];
    #pragma unroll
    for (int kk = 0; kk < 8; kk++){
        uint32_t addr = (uint32_t)__cvta_generic_to_shared(
            &Ps[(rowbase + a_r) * ESTR + kk*8 + a_coff]);
        asm volatile("ldmatrix.sync.aligned.m8n8.x4.shared.b16 {%0,%1,%2,%3}, [%4];"
            : "=r"(qa[kk][0]), "=r"(qa[kk][1]), "=r"(qa[kk][2]), "=r"(qa[kk][3])
            : "r"(addr));
    }

    const int r = lane >> 2;
    const int cq = (lane & 3) << 1;
    const int tA = t0 + rowbase + r;
    const int tB = tA + 8;
    const float gA = gain[h*Tt + tA], bA = bias[h*Tt + tA];
    const float gB = gain[h*Tt + tB], bB = bias[h*Tt + tB];
    const int twmax = t0 + rowbase + 15;

    float oacc[8][4] = {};
    float psumA = 0.f, psumB = 0.f;

    for (int s0 = 0; s0 < t0 + 128; s0 += 64){
        __syncthreads();
        {
            const int lr = tid >> 2, cg = (tid & 3) * 16;
            const float* ep = E + ((size_t)(h*Tt + s0 + lr)) * Dd + cg;
            #pragma unroll
            for (int j = 0; j < 4; j++){
                float4 v4 = *(const float4*)(ep + j*4);
                *(float4*)&Es[lr*ESTR + cg + j*4] = make_float4(
                    to_tf32(v4.x), to_tf32(v4.y), to_tf32(v4.z), to_tf32(v4.w));
            }
            const float* vp = V + ((size_t)(b*Tt + s0 + lr)) * QVLD + h*Dd + cg;
            #pragma unroll
            for (int j = 0; j < 4; j++){
                float4 v4 = *(const float4*)(vp + j*4);
                Vt[(cg+j*4+0)*ESTR + lr] = to_tf32(v4.x);
                Vt[(cg+j*4+1)*ESTR + lr] = to_tf32(v4.y);
                Vt[(cg+j*4+2)*ESTR + lr] = to_tf32(v4.z);
                Vt[(cg+j*4+3)*ESTR + lr] = to_tf32(v4.w);
            }
        }
        __syncthreads();

        if (s0 > twmax) continue;

        float sacc[8][4] = {};
        #pragma unroll
        for (int kk = 0; kk < 8; kk++){
            uint32_t bfr[4][4];
            #pragma unroll
            for (int np = 0; np < 4; np++){
                uint32_t addr = (uint32_t)__cvta_generic_to_shared(
                    &Es[(np*16 + b_r) * ESTR + kk*8 + b_coff]);
                asm volatile("ldmatrix.sync.aligned.m8n8.x4.shared.b16 {%0,%1,%2,%3}, [%4];"
                    : "=r"(bfr[np][0]), "=r"(bfr[np][1]), "=r"(bfr[np][2]), "=r"(bfr[np][3])
                    : "r"(addr));
            }
            #pragma unroll
            for (int nt = 0; nt < 8; nt++){
                uint32_t b0 = bfr[nt >> 1][(nt & 1) * 2];
                uint32_t b1 = bfr[nt >> 1][(nt & 1) * 2 + 1];
                asm volatile(
                    "mma.sync.aligned.m16n8k8.row.col.f32.tf32.tf32.f32 "
                    "{%0,%1,%2,%3},{%4,%5,%6,%7},{%8,%9},{%0,%1,%2,%3};"
                    : "+f"(sacc[nt][0]), "+f"(sacc[nt][1]),
                      "+f"(sacc[nt][2]), "+f"(sacc[nt][3])
                    : "r"(qa[kk][0]), "r"(qa[kk][1]), "r"(qa[kk][2]), "r"(qa[kk][3]),
                      "r"(b0), "r"(b1));
            }
        }

        #pragma unroll
        for (int nt = 0; nt < 8; nt++){
            int sb = s0 + nt*8 + cq;
            float p00 = lif_p(fmaf(gA, sacc[nt][0], bA)); if (sb     > tA) p00 = 0.f;
            float p01 = lif_p(fmaf(gA, sacc[nt][1], bA)); if (sb + 1 > tA) p01 = 0.f;
            float p10 = lif_p(fmaf(gB, sacc[nt][2], bB)); if (sb     > tB) p10 = 0.f;
            float p11 = lif_p(fmaf(gB, sacc[nt][3], bB)); if (sb + 1 > tB) p11 = 0.f;
            psumA += p00 + p01;
            psumB += p10 + p11;
            *(float2*)&Ps[(rowbase + r    )*ESTR + nt*8 + cq] = make_float2(to_tf32(p00), to_tf32(p01));
            *(float2*)&Ps[(rowbase + r + 8)*ESTR + nt*8 + cq] = make_float2(to_tf32(p10), to_tf32(p11));
        }
        __syncwarp();

        #pragma unroll
        for (int kk = 0; kk < 8; kk++){
            uint32_t afr[4];
            {
                uint32_t addr = (uint32_t)__cvta_generic_to_shared(
                    &Ps[(rowbase + a_r) * ESTR + kk*8 + a_coff]);
                asm volatile("ldmatrix.sync.aligned.m8n8.x4.shared.b16 {%0,%1,%2,%3}, [%4];"
                    : "=r"(afr[0]), "=r"(afr[1]), "=r"(afr[2]), "=r"(afr[3])
                    : "r"(addr));
            }
            uint32_t bfr[4][4];
            #pragma unroll
            for (int np = 0; np < 4; np++){
                uint32_t addr = (uint32_t)__cvta_generic_to_shared(
                    &Vt[(np*16 + b_r) * ESTR + kk*8 + b_coff]);
                asm volatile("ldmatrix.sync.aligned.m8n8.x4.shared.b16 {%0,%1,%2,%3}, [%4];"
                    : "=r"(bfr[np][0]), "=r"(bfr[np][1]), "=r"(bfr[np][2]), "=r"(bfr[np][3])
                    : "r"(addr));
            }
            #pragma unroll
            for (int nt = 0; nt < 8; nt++){
                uint32_t b0 = bfr[nt >> 1][(nt & 1) * 2];
                uint32_t b1 = bfr[nt >> 1][(nt & 1) * 2 + 1];
                asm volatile(
                    "mma.sync.aligned.m16n8k8.row.col.f32.tf32.tf32.f32 "
                    "{%0,%1,%2,%3},{%4,%5,%6,%7},{%8,%9},{%0,%1,%2,%3};"
                    : "+f"(oacc[nt][0]), "+f"(oacc[nt][1]),
                      "+f"(oacc[nt][2]), "+f"(oacc[nt][3])
                    : "r"(afr[0]), "r"(afr[1]), "r"(afr[2]), "r"(afr[3]),
                      "r"(b0), "r"(b1));
            }
        }
    }

    psumA += __shfl_xor_sync(0xffffffffu, psumA, 1);
    psumA += __shfl_xor_sync(0xffffffffu, psumA, 2);
    psumB += __shfl_xor_sync(0xffffffffu, psumB, 1);
    psumB += __shfl_xor_sync(0xffffffffu, psumB, 2);
    float invA = 1.0f / psumA;
    float invB = 1.0f / psumB;

    float* opA = out + ((size_t)(b*Tt + tA)) * Cc + h*Dd;
    float* opB = out + ((size_t)(b*Tt + tB)) * Cc + h*Dd;
    #pragma unroll
    for (int nt = 0; nt < 8; nt++){
        int d = nt*8 + cq;
        *(float2*)&opA[d] = make_float2(oacc[nt][0]*invA, oacc[nt][1]*invA);
        *(float2*)&opB[d] = make_float2(oacc[nt][2]*invB, oacc[nt][3]*invB);
    }
}

// ======================== launch ========================
extern "C" void kernel_launch(void* const* d_in, const int* in_sizes, int n_in,
                              void* d_out, int out_size){
    const float* x      = (const float*)d_in[0];
    const float* ln1_g  = (const float*)d_in[1];
    const float* ln1_b  = (const float*)d_in[2];
    const float* qkv_w  = (const float*)d_in[3];
    const float* qkv_b  = (const float*)d_in[4];
    const float* out_w  = (const float*)d_in[5];
    const float* out_b  = (const float*)d_in[6];
    const float* ln2_g  = (const float*)d_in[7];
    const float* ln2_b  = (const float*)d_in[8];
    const float* mlp_w1 = (const float*)d_in[9];
    const float* mlp_b1 = (const float*)d_in[10];
    const float* mlp_w2 = (const float*)d_in[11];
    const float* mlp_b2 = (const float*)d_in[12];
    const float* enc    = (const float*)d_in[13];
    const float* gain   = (const float*)d_in[14];
    const float* battn  = (const float*)d_in[15];
    float* outp = (float*)d_out;

    float *xn, *qv, *att, *x1, *hbuf, *qvb;
    __half *wqv, *wo, *w1, *w2;
    cudaGetSymbolAddress((void**)&xn,   g_xn);
    cudaGetSymbolAddress((void**)&qv,   g_qv);
    cudaGetSymbolAddress((void**)&att,  g_att);
    cudaGetSymbolAddress((void**)&x1,   g_x1);
    cudaGetSymbolAddress((void**)&hbuf, g_h);
    cudaGetSymbolAddress((void**)&wqv,  g_wqv);
    cudaGetSymbolAddress((void**)&wo,   g_wo);
    cudaGetSymbolAddress((void**)&w1,   g_w1);
    cudaGetSymbolAddress((void**)&w2,   g_w2);
    cudaGetSymbolAddress((void**)&qvb,  g_qvb);

    cudaFuncSetAttribute(attn_tc, cudaFuncAttributeMaxDynamicSharedMemorySize, ATTN_SMEM);

    const int M = Bb * Tt;   // 4096

    // one-time-per-launch prep
    pack_bias<<<8, 256>>>(qkv_b, qvb);
    transpose_h<<<dim3(Cc/32,   Cc/32),   dim3(32,8)>>>(qkv_w,        3*Cc, wqv,          Cc);
    transpose_h<<<dim3(Cc/32,   Cc/32),   dim3(32,8)>>>(qkv_w + 2*Cc, 3*Cc, wqv + Cc*Cc,  Cc);
    transpose_h<<<dim3(Cc/32,   Cc/32),   dim3(32,8)>>>(out_w,        Cc,   wo,           Cc);
    transpose_h<<<dim3(4*Cc/32, Cc/32),   dim3(32,8)>>>(mlp_w1,       4*Cc, w1,           Cc);
    transpose_h<<<dim3(Cc/32,   4*Cc/32), dim3(32,8)>>>(mlp_w2,       Cc,   w2,           4*Cc);

    ln_kernel<<<M, 256>>>(x, ln1_g, ln1_b, xn);
    // fused Q|V projection: N=2048
    gemm_h<<<dim3(2*Cc/128, M/128), 256>>>(xn, wqv, qvb, nullptr, qv, 2*Cc, Cc, 0);
    attn_tc<<<dim3(Tt/128, Bb*Hh), 256, ATTN_SMEM>>>(qv, qv + Cc, enc, gain, battn, att);
    gemm_h<<<dim3(Cc/128, M/128), 256>>>(att, wo, out_b, x, x1, Cc, Cc, 0);
    ln_kernel<<<M, 256>>>(x1, ln2_g, ln2_b, xn);
    gemm_h<<<dim3(4*Cc/128, M/128), 256>>>(xn, w1, mlp_b1, nullptr, hbuf, 4*Cc, Cc, 1);
    gemm_h<<<dim3(Cc/128, M/128), 256>>>(hbuf, w2, mlp_b2, x1, outp, Cc, 4*Cc, 0);
}

// round 6
// speedup vs baseline: 4.2365x; 1.3765x over previous
#include <cuda_runtime.h>
#include <cuda_fp16.h>
#include <math.h>
#include <stdint.h>

#define Bb 2
#define Tt 2048
#define Cc 1024
#define Hh 16
#define Dd 64

__device__ __half g_xn [Bb*Tt*Cc];       // LN out (half)
__device__ __half g_qv [Bb*Tt*2*Cc];     // fused Q|V (half), row stride 2048
__device__ __half g_att[Bb*Tt*Cc];       // attention out (half)
__device__ float  g_x1 [Bb*Tt*Cc];       // x + attn proj (fp32)
__device__ __half g_h  [Bb*Tt*4*Cc];     // gelu(mlp1) (half)
__device__ __half g_wqv[2*Cc*Cc];        // weights [N][K] half
__device__ __half g_wo [Cc*Cc];
__device__ __half g_w1 [4*Cc*Cc];
__device__ __half g_w2 [Cc*4*Cc];
__device__ float  g_qvb[2*Cc];

__device__ __forceinline__ float to_tf32(float x){
    float r; asm("cvt.rna.tf32.f32 %0, %1;" : "=f"(r) : "f"(x)); return r;
}

// ======================== prep kernels ========================
__global__ void pack_bias(const float* __restrict__ qkv_b, float* __restrict__ qvb){
    int i = blockIdx.x * 256 + threadIdx.x;
    qvb[i] = (i < Cc) ? qkv_b[i] : qkv_b[i + Cc];
}

__global__ void transpose_h(const float* __restrict__ W, int ldw,
                            __half* __restrict__ Wt, int K){
    __shared__ float t[32][33];
    int n0 = blockIdx.x * 32, k0 = blockIdx.y * 32;
    int tx = threadIdx.x, ty = threadIdx.y;
    #pragma unroll
    for (int i = 0; i < 4; i++)
        t[ty + i*8][tx] = W[(size_t)(k0 + ty + i*8) * ldw + n0 + tx];
    __syncthreads();
    #pragma unroll
    for (int i = 0; i < 4; i++)
        Wt[(size_t)(n0 + ty + i*8) * K + k0 + tx] = __float2half_rn(t[tx][ty + i*8]);
}

// ======================== block reduce / LayerNorm (half out) ========================
__device__ __forceinline__ float block_sum(float v, volatile float* red){
    #pragma unroll
    for (int o = 16; o; o >>= 1) v += __shfl_xor_sync(0xffffffffu, v, o);
    int lane = threadIdx.x & 31, w = threadIdx.x >> 5;
    if (lane == 0) red[w] = v;
    __syncthreads();
    if (w == 0){
        v = (lane < 8) ? red[lane] : 0.f;
        #pragma unroll
        for (int o = 4; o; o >>= 1) v += __shfl_xor_sync(0xffffffffu, v, o);
    }
    return v;
}

__global__ void ln_kernel(const float* __restrict__ x, const float* __restrict__ g,
                          const float* __restrict__ b, __half* __restrict__ out){
    __shared__ float red[8];
    __shared__ float s_mu, s_rs;
    int row = blockIdx.x, tid = threadIdx.x;
    const float4 v = ((const float4*)(x + (size_t)row * Cc))[tid];
    float s = v.x + v.y + v.z + v.w;
    s = block_sum(s, red);
    if (tid == 0) s_mu = s * (1.0f / Cc);
    __syncthreads();
    float mu = s_mu;
    float dx = v.x - mu, dy = v.y - mu, dz = v.z - mu, dw = v.w - mu;
    float sq = dx*dx + dy*dy + dz*dz + dw*dw;
    sq = block_sum(sq, red);
    if (tid == 0) s_rs = rsqrtf(sq * (1.0f / Cc) + 1e-5f);
    __syncthreads();
    float rs = s_rs;
    float4 gg = ((const float4*)g)[tid], bb = ((const float4*)b)[tid];
    __half2 h0 = __floats2half2_rn(dx * rs * gg.x + bb.x, dy * rs * gg.y + bb.y);
    __half2 h1 = __floats2half2_rn(dz * rs * gg.z + bb.z, dw * rs * gg.w + bb.w);
    __half2* op = (__half2*)(out + (size_t)row * Cc);
    op[tid*2]     = h0;
    op[tid*2 + 1] = h1;
}

// ======================== fp16 tensor GEMM, cp.async 4-stage ========================
// out[M,N] = A[M,K](f16) @ Bt[N,K](f16)^T + bias (+resid)(+gelu)
// BM=BN=128, BK=32, 256 thr (8 warps 2m x 4n, warp tile 64x32), m16n8k16.
#define HSTR 40
#define NSTG 4
#define STG_H (128*HSTR)
#define GH_SMEM (NSTG * STG_H * 2 * 2)   // 81920 bytes

#define CPA16(dst, src) \
    asm volatile("cp.async.cg.shared.global [%0], [%1], 16;" :: "r"(dst), "l"(src) : "memory")

template<bool OUT_HALF>
__global__ __launch_bounds__(256) void gemm_h(
        const __half* __restrict__ A,
        const __half* __restrict__ Bt,
        const float* __restrict__ bias,
        const float* __restrict__ resid,
        void* __restrict__ outv,
        int N, int K, int do_gelu){
    extern __shared__ __half smh[];
    __half* As = smh;
    __half* Bs = smh + NSTG * STG_H;
    const int tid = threadIdx.x;
    const int lane = tid & 31, w = tid >> 5;
    const int warpM = (w & 1) * 64, warpN = (w >> 1) * 32;
    const int row0 = blockIdx.y * 128, col0 = blockIdx.x * 128;

    const int sr = tid >> 1;
    const int kh = (tid & 1) * 16;
    const __half* Ap = A + (size_t)(row0 + sr) * K + kh;
    const __half* Bp = Bt + (size_t)(col0 + sr) * K + kh;
    const uint32_t adst = (uint32_t)__cvta_generic_to_shared(&As[sr*HSTR + kh]);
    const uint32_t bdst = (uint32_t)__cvta_generic_to_shared(&Bs[sr*HSTR + kh]);

    auto load_chunk = [&](int c, int s){
        uint32_t ao = adst + s * STG_H * 2;
        uint32_t bo = bdst + s * STG_H * 2;
        const __half* ag = Ap + c * 32;
        const __half* bg = Bp + c * 32;
        CPA16(ao, ag); CPA16(ao + 16, ag + 8);
        CPA16(bo, bg); CPA16(bo + 16, bg + 8);
        asm volatile("cp.async.commit_group;" ::: "memory");
    };

    float acc[4][4][4] = {};

    const int a_row = lane & 15;
    const int a_col = (lane >> 4) * 8;
    const int b_row = (lane & 7) + ((lane >> 4) << 3);
    const int b_col = ((lane >> 3) & 1) * 8;

    auto compute = [&](int s){
        const __half* Ab = As + s * STG_H;
        const __half* Bb2 = Bs + s * STG_H;
        #pragma unroll
        for (int kk = 0; kk < 2; kk++){
            uint32_t afr[4][4];
            #pragma unroll
            for (int mt = 0; mt < 4; mt++){
                uint32_t addr = (uint32_t)__cvta_generic_to_shared(
                    &Ab[(warpM + mt*16 + a_row) * HSTR + kk*16 + a_col]);
                asm volatile("ldmatrix.sync.aligned.m8n8.x4.shared.b16 {%0,%1,%2,%3}, [%4];"
                    : "=r"(afr[mt][0]), "=r"(afr[mt][1]), "=r"(afr[mt][2]), "=r"(afr[mt][3])
                    : "r"(addr));
            }
            uint32_t bfr[2][4];
            #pragma unroll
            for (int ng = 0; ng < 2; ng++){
                uint32_t addr = (uint32_t)__cvta_generic_to_shared(
                    &Bb2[(warpN + ng*16 + b_row) * HSTR + kk*16 + b_col]);
                asm volatile("ldmatrix.sync.aligned.m8n8.x4.shared.b16 {%0,%1,%2,%3}, [%4];"
                    : "=r"(bfr[ng][0]), "=r"(bfr[ng][1]), "=r"(bfr[ng][2]), "=r"(bfr[ng][3])
                    : "r"(addr));
            }
            #pragma unroll
            for (int mt = 0; mt < 4; mt++)
                #pragma unroll
                for (int nt = 0; nt < 4; nt++){
                    uint32_t b0 = bfr[nt >> 1][(nt & 1) * 2];
                    uint32_t b1 = bfr[nt >> 1][(nt & 1) * 2 + 1];
                    asm volatile(
                        "mma.sync.aligned.m16n8k16.row.col.f32.f16.f16.f32 "
                        "{%0,%1,%2,%3},{%4,%5,%6,%7},{%8,%9},{%0,%1,%2,%3};"
                        : "+f"(acc[mt][nt][0]), "+f"(acc[mt][nt][1]),
                          "+f"(acc[mt][nt][2]), "+f"(acc[mt][nt][3])
                        : "r"(afr[mt][0]), "r"(afr[mt][1]), "r"(afr[mt][2]), "r"(afr[mt][3]),
                          "r"(b0), "r"(b1));
                }
        }
    };

    const int ntiles = K / 32;
    load_chunk(0, 0); load_chunk(1, 1); load_chunk(2, 2);
    for (int t = 0; t < ntiles; t++){
        asm volatile("cp.async.wait_group 2;" ::: "memory");
        __syncthreads();
        if (t + 3 < ntiles) load_chunk(t + 3, (t + 3) & 3);
        compute(t & 3);
    }

    // epilogue
    #pragma unroll
    for (int mt = 0; mt < 4; mt++){
        #pragma unroll
        for (int nt = 0; nt < 4; nt++){
            int rr = row0 + warpM + mt*16 + (lane >> 2);
            int cc = col0 + warpN + nt*8 + (lane & 3) * 2;
            #pragma unroll
            for (int half = 0; half < 2; half++){
                int r = rr + half * 8;
                float v0 = acc[mt][nt][half*2]     + bias[cc];
                float v1 = acc[mt][nt][half*2 + 1] + bias[cc + 1];
                if (resid){
                    const float2 rv = *(const float2*)&resid[(size_t)r * N + cc];
                    v0 += rv.x; v1 += rv.y;
                }
                if (do_gelu){
                    v0 = 0.5f * v0 * (1.f + erff(v0 * 0.70710678118f));
                    v1 = 0.5f * v1 * (1.f + erff(v1 * 0.70710678118f));
                }
                if (OUT_HALF){
                    *(__half2*)&((__half*)outv)[(size_t)r * N + cc] = __floats2half2_rn(v0, v1);
                } else {
                    *(float2*)&((float*)outv)[(size_t)r * N + cc] = make_float2(v0, v1);
                }
            }
        }
    }
}

// ======================== Attention ========================
// MMA1 (Q.E^T) fp16 m16n8k16; MMA2 (P.V^T) tf32 m16n8k8.
// smem: Vt float[64][68]; Ps float[128][68] (alias: Q half staging [128][72]);
//       EsH half[64][72].
#define ESTR 68
#define HQ 72
#define QVLD (2*Cc)
#define ATTN_SMEM ((64*ESTR + 128*ESTR)*4 + 64*HQ*2)

__device__ __forceinline__ float lif_p(float I){
    if (I > 1.0000001f){
        float u = __fdividef(1.0f, I);
        float d = fmaf(-0.02f, __logf(1.0f - u), 0.002f);
        return __expf(__fdividef(0.125f, d));
    }
    return 1.0f;
}

__global__ __launch_bounds__(256) void attn_tc(
        const __half* __restrict__ Q, const __half* __restrict__ V,
        const float* __restrict__ E, const float* __restrict__ gain,
        const float* __restrict__ bias, __half* __restrict__ out){
    extern __shared__ float sm[];
    float* Vt  = sm;                          // 64*68 floats
    float* Ps  = sm + 64*ESTR;                // 128*68 floats
    __half* EsH = (__half*)(sm + 64*ESTR + 128*ESTR);   // 64*72 halves
    __half* PsH = (__half*)Ps;                // Q staging [128][HQ]

    const int tid = threadIdx.x;
    const int lane = tid & 31, w = tid >> 5;
    const int bh = blockIdx.y, b = bh >> 4, h = bh & 15;
    const int t0 = (gridDim.x - 1 - blockIdx.x) << 7;
    const int rowbase = w << 4;

    // fp16 A-fragment mapping (m16n8k16)
    const int a_row = lane & 15;
    const int a_col = (lane >> 4) * 8;
    const int b_row = (lane & 7) + ((lane >> 4) << 3);
    const int b_col = ((lane >> 3) & 1) * 8;
    // tf32 fragment mapping (m16n8k8)
    const int a_r    = (lane & 7) + ((lane >> 3) & 1) * 8;
    const int a_coff = (lane >> 4) * 4;
    const int t_b_r    = (lane & 7) + (lane >> 4) * 8;
    const int t_b_coff = ((lane >> 3) & 1) * 4;

    // ---- stage Q tile (half, straight copy)
    {
        const int qr = tid >> 1, qc = (tid & 1) * 32;
        const __half* qp = Q + ((size_t)(b*Tt + t0 + qr)) * QVLD + h*Dd + qc;
        #pragma unroll
        for (int j = 0; j < 4; j++)
            *(uint4*)&PsH[qr*HQ + qc + j*8] = *(const uint4*)(qp + j*8);
    }
    __syncthreads();

    // ---- persistent Q fragments: 4 k16-steps
    uint32_t qa[4][4];
    #pragma unroll
    for (int kk = 0; kk < 4; kk++){
        uint32_t addr = (uint32_t)__cvta_generic_to_shared(
            &PsH[(rowbase + a_row) * HQ + kk*16 + a_col]);
        asm volatile("ldmatrix.sync.aligned.m8n8.x4.shared.b16 {%0,%1,%2,%3}, [%4];"
            : "=r"(qa[kk][0]), "=r"(qa[kk][1]), "=r"(qa[kk][2]), "=r"(qa[kk][3])
            : "r"(addr));
    }

    const int r = lane >> 2;
    const int cq = (lane & 3) << 1;
    const int tA = t0 + rowbase + r;
    const int tB = tA + 8;
    const float gA = gain[h*Tt + tA], bA = bias[h*Tt + tA];
    const float gB = gain[h*Tt + tB], bB = bias[h*Tt + tB];
    const int twmax = t0 + rowbase + 15;

    float oacc[8][4] = {};
    float psumA = 0.f, psumB = 0.f;

    for (int s0 = 0; s0 < t0 + 128; s0 += 64){
        __syncthreads();
        // ---- stage E (half) and V^T (float/tf32)
        {
            const int lr = tid >> 2, cg = (tid & 3) * 16;
            const float* ep = E + ((size_t)(h*Tt + s0 + lr)) * Dd + cg;
            uint32_t hp[8];
            #pragma unroll
            for (int j = 0; j < 4; j++){
                float4 v4 = *(const float4*)(ep + j*4);
                __half2 lo = __floats2half2_rn(v4.x, v4.y);
                __half2 hi = __floats2half2_rn(v4.z, v4.w);
                hp[j*2]   = *(uint32_t*)&lo;
                hp[j*2+1] = *(uint32_t*)&hi;
            }
            *(uint4*)&EsH[lr*HQ + cg]     = make_uint4(hp[0], hp[1], hp[2], hp[3]);
            *(uint4*)&EsH[lr*HQ + cg + 8] = make_uint4(hp[4], hp[5], hp[6], hp[7]);

            const __half* vp = V + ((size_t)(b*Tt + s0 + lr)) * QVLD + h*Dd + cg;
            uint4 u0 = *(const uint4*)vp;
            uint4 u1 = *(const uint4*)(vp + 8);
            const __half2* hv0 = (const __half2*)&u0;
            const __half2* hv1 = (const __half2*)&u1;
            #pragma unroll
            for (int j = 0; j < 4; j++){
                float2 f = __half22float2(hv0[j]);
                Vt[(cg + j*2    )*ESTR + lr] = f.x;
                Vt[(cg + j*2 + 1)*ESTR + lr] = f.y;
            }
            #pragma unroll
            for (int j = 0; j < 4; j++){
                float2 f = __half22float2(hv1[j]);
                Vt[(cg + 8 + j*2    )*ESTR + lr] = f.x;
                Vt[(cg + 8 + j*2 + 1)*ESTR + lr] = f.y;
            }
        }
        __syncthreads();

        if (s0 > twmax) continue;

        // ---- MMA1 fp16: S[16x64] = Q . E^T
        float sacc[8][4] = {};
        #pragma unroll
        for (int kk = 0; kk < 4; kk++){
            uint32_t bfr[4][4];
            #pragma unroll
            for (int ng = 0; ng < 4; ng++){
                uint32_t addr = (uint32_t)__cvta_generic_to_shared(
                    &EsH[(ng*16 + b_row) * HQ + kk*16 + b_col]);
                asm volatile("ldmatrix.sync.aligned.m8n8.x4.shared.b16 {%0,%1,%2,%3}, [%4];"
                    : "=r"(bfr[ng][0]), "=r"(bfr[ng][1]), "=r"(bfr[ng][2]), "=r"(bfr[ng][3])
                    : "r"(addr));
            }
            #pragma unroll
            for (int nt = 0; nt < 8; nt++){
                uint32_t b0 = bfr[nt >> 1][(nt & 1) * 2];
                uint32_t b1 = bfr[nt >> 1][(nt & 1) * 2 + 1];
                asm volatile(
                    "mma.sync.aligned.m16n8k16.row.col.f32.f16.f16.f32 "
                    "{%0,%1,%2,%3},{%4,%5,%6,%7},{%8,%9},{%0,%1,%2,%3};"
                    : "+f"(sacc[nt][0]), "+f"(sacc[nt][1]),
                      "+f"(sacc[nt][2]), "+f"(sacc[nt][3])
                    : "r"(qa[kk][0]), "r"(qa[kk][1]), "r"(qa[kk][2]), "r"(qa[kk][3]),
                      "r"(b0), "r"(b1));
            }
        }

        // ---- LIF + causal -> Ps (tf32), own warp rows
        #pragma unroll
        for (int nt = 0; nt < 8; nt++){
            int sb = s0 + nt*8 + cq;
            float p00 = lif_p(fmaf(gA, sacc[nt][0], bA)); if (sb     > tA) p00 = 0.f;
            float p01 = lif_p(fmaf(gA, sacc[nt][1], bA)); if (sb + 1 > tA) p01 = 0.f;
            float p10 = lif_p(fmaf(gB, sacc[nt][2], bB)); if (sb     > tB) p10 = 0.f;
            float p11 = lif_p(fmaf(gB, sacc[nt][3], bB)); if (sb + 1 > tB) p11 = 0.f;
            psumA += p00 + p01;
            psumB += p10 + p11;
            *(float2*)&Ps[(rowbase + r    )*ESTR + nt*8 + cq] = make_float2(to_tf32(p00), to_tf32(p01));
            *(float2*)&Ps[(rowbase + r + 8)*ESTR + nt*8 + cq] = make_float2(to_tf32(p10), to_tf32(p11));
        }
        __syncwarp();

        // ---- MMA2 tf32: O += P . V
        #pragma unroll
        for (int kk = 0; kk < 8; kk++){
            uint32_t afr[4];
            {
                uint32_t addr = (uint32_t)__cvta_generic_to_shared(
                    &Ps[(rowbase + a_r) * ESTR + kk*8 + a_coff]);
                asm volatile("ldmatrix.sync.aligned.m8n8.x4.shared.b16 {%0,%1,%2,%3}, [%4];"
                    : "=r"(afr[0]), "=r"(afr[1]), "=r"(afr[2]), "=r"(afr[3])
                    : "r"(addr));
            }
            uint32_t bfr[4][4];
            #pragma unroll
            for (int np = 0; np < 4; np++){
                uint32_t addr = (uint32_t)__cvta_generic_to_shared(
                    &Vt[(np*16 + t_b_r) * ESTR + kk*8 + t_b_coff]);
                asm volatile("ldmatrix.sync.aligned.m8n8.x4.shared.b16 {%0,%1,%2,%3}, [%4];"
                    : "=r"(bfr[np][0]), "=r"(bfr[np][1]), "=r"(bfr[np][2]), "=r"(bfr[np][3])
                    : "r"(addr));
            }
            #pragma unroll
            for (int nt = 0; nt < 8; nt++){
                uint32_t b0 = bfr[nt >> 1][(nt & 1) * 2];
                uint32_t b1 = bfr[nt >> 1][(nt & 1) * 2 + 1];
                asm volatile(
                    "mma.sync.aligned.m16n8k8.row.col.f32.tf32.tf32.f32 "
                    "{%0,%1,%2,%3},{%4,%5,%6,%7},{%8,%9},{%0,%1,%2,%3};"
                    : "+f"(oacc[nt][0]), "+f"(oacc[nt][1]),
                      "+f"(oacc[nt][2]), "+f"(oacc[nt][3])
                    : "r"(afr[0]), "r"(afr[1]), "r"(afr[2]), "r"(afr[3]),
                      "r"(b0), "r"(b1));
            }
        }
    }

    psumA += __shfl_xor_sync(0xffffffffu, psumA, 1);
    psumA += __shfl_xor_sync(0xffffffffu, psumA, 2);
    psumB += __shfl_xor_sync(0xffffffffu, psumB, 1);
    psumB += __shfl_xor_sync(0xffffffffu, psumB, 2);
    float invA = 1.0f / psumA;
    float invB = 1.0f / psumB;

    __half* opA = out + ((size_t)(b*Tt + tA)) * Cc + h*Dd;
    __half* opB = out + ((size_t)(b*Tt + tB)) * Cc + h*Dd;
    #pragma unroll
    for (int nt = 0; nt < 8; nt++){
        int d = nt*8 + cq;
        *(__half2*)&opA[d] = __floats2half2_rn(oacc[nt][0]*invA, oacc[nt][1]*invA);
        *(__half2*)&opB[d] = __floats2half2_rn(oacc[nt][2]*invB, oacc[nt][3]*invB);
    }
}

// ======================== launch ========================
extern "C" void kernel_launch(void* const* d_in, const int* in_sizes, int n_in,
                              void* d_out, int out_size){
    const float* x      = (const float*)d_in[0];
    const float* ln1_g  = (const float*)d_in[1];
    const float* ln1_b  = (const float*)d_in[2];
    const float* qkv_w  = (const float*)d_in[3];
    const float* qkv_b  = (const float*)d_in[4];
    const float* out_w  = (const float*)d_in[5];
    const float* out_b  = (const float*)d_in[6];
    const float* ln2_g  = (const float*)d_in[7];
    const float* ln2_b  = (const float*)d_in[8];
    const float* mlp_w1 = (const float*)d_in[9];
    const float* mlp_b1 = (const float*)d_in[10];
    const float* mlp_w2 = (const float*)d_in[11];
    const float* mlp_b2 = (const float*)d_in[12];
    const float* enc    = (const float*)d_in[13];
    const float* gain   = (const float*)d_in[14];
    const float* battn  = (const float*)d_in[15];
    float* outp = (float*)d_out;

    __half *xn, *qv, *att, *hbuf, *wqv, *wo, *w1, *w2;
    float *x1, *qvb;
    cudaGetSymbolAddress((void**)&xn,   g_xn);
    cudaGetSymbolAddress((void**)&qv,   g_qv);
    cudaGetSymbolAddress((void**)&att,  g_att);
    cudaGetSymbolAddress((void**)&x1,   g_x1);
    cudaGetSymbolAddress((void**)&hbuf, g_h);
    cudaGetSymbolAddress((void**)&wqv,  g_wqv);
    cudaGetSymbolAddress((void**)&wo,   g_wo);
    cudaGetSymbolAddress((void**)&w1,   g_w1);
    cudaGetSymbolAddress((void**)&w2,   g_w2);
    cudaGetSymbolAddress((void**)&qvb,  g_qvb);

    cudaFuncSetAttribute(attn_tc,       cudaFuncAttributeMaxDynamicSharedMemorySize, ATTN_SMEM);
    cudaFuncSetAttribute(gemm_h<true>,  cudaFuncAttributeMaxDynamicSharedMemorySize, GH_SMEM);
    cudaFuncSetAttribute(gemm_h<false>, cudaFuncAttributeMaxDynamicSharedMemorySize, GH_SMEM);

    const int M = Bb * Tt;   // 4096

    pack_bias<<<8, 256>>>(qkv_b, qvb);
    transpose_h<<<dim3(Cc/32,   Cc/32),   dim3(32,8)>>>(qkv_w,        3*Cc, wqv,         Cc);
    transpose_h<<<dim3(Cc/32,   Cc/32),   dim3(32,8)>>>(qkv_w + 2*Cc, 3*Cc, wqv + Cc*Cc, Cc);
    transpose_h<<<dim3(Cc/32,   Cc/32),   dim3(32,8)>>>(out_w,        Cc,   wo,          Cc);
    transpose_h<<<dim3(4*Cc/32, Cc/32),   dim3(32,8)>>>(mlp_w1,       4*Cc, w1,          Cc);
    transpose_h<<<dim3(Cc/32,   4*Cc/32), dim3(32,8)>>>(mlp_w2,       Cc,   w2,          4*Cc);

    ln_kernel<<<M, 256>>>(x, ln1_g, ln1_b, xn);
    gemm_h<true ><<<dim3(2*Cc/128, M/128), 256, GH_SMEM>>>(xn, wqv, qvb, nullptr, qv, 2*Cc, Cc, 0);
    attn_tc<<<dim3(Tt/128, Bb*Hh), 256, ATTN_SMEM>>>(qv, qv + Cc, enc, gain, battn, att);
    gemm_h<false><<<dim3(Cc/128, M/128), 256, GH_SMEM>>>(att, wo, out_b, x, x1, Cc, Cc, 0);
    ln_kernel<<<M, 256>>>(x1, ln2_g, ln2_b, xn);
    gemm_h<true ><<<dim3(4*Cc/128, M/128), 256, GH_SMEM>>>(xn, w1, mlp_b1, nullptr, hbuf, 4*Cc, Cc, 1);
    gemm_h<false><<<dim3(Cc/128, M/128), 256, GH_SMEM>>>(hbuf, w2, mlp_b2, x1, outp, Cc, 4*Cc, 0);
}

// round 7
// speedup vs baseline: 4.4402x; 1.0481x over previous
#include <cuda_runtime.h>
#include <cuda_fp16.h>
#include <math.h>
#include <stdint.h>

#define Bb 2
#define Tt 2048
#define Cc 1024
#define Hh 16
#define Dd 64

__device__ __half g_xn [Bb*Tt*Cc];
__device__ __half g_qv [Bb*Tt*2*Cc];
__device__ __half g_att[Bb*Tt*Cc];
__device__ float  g_x1 [Bb*Tt*Cc];
__device__ __half g_h  [Bb*Tt*4*Cc];
__device__ __half g_wqv[2*Cc*Cc];
__device__ __half g_wo [Cc*Cc];
__device__ __half g_w1 [4*Cc*Cc];
__device__ __half g_w2 [Cc*4*Cc];
__device__ float  g_qvb[2*Cc];

// ======================== prep kernels ========================
__global__ void pack_bias(const float* __restrict__ qkv_b, float* __restrict__ qvb){
    int i = blockIdx.x * 256 + threadIdx.x;
    qvb[i] = (i < Cc) ? qkv_b[i] : qkv_b[i + Cc];
}

__global__ void transpose_h(const float* __restrict__ W, int ldw,
                            __half* __restrict__ Wt, int K){
    __shared__ float t[32][33];
    int n0 = blockIdx.x * 32, k0 = blockIdx.y * 32;
    int tx = threadIdx.x, ty = threadIdx.y;
    #pragma unroll
    for (int i = 0; i < 4; i++)
        t[ty + i*8][tx] = W[(size_t)(k0 + ty + i*8) * ldw + n0 + tx];
    __syncthreads();
    #pragma unroll
    for (int i = 0; i < 4; i++)
        Wt[(size_t)(n0 + ty + i*8) * K + k0 + tx] = __float2half_rn(t[tx][ty + i*8]);
}

// ======================== block reduce / LayerNorm ========================
__device__ __forceinline__ float block_sum(float v, volatile float* red){
    #pragma unroll
    for (int o = 16; o; o >>= 1) v += __shfl_xor_sync(0xffffffffu, v, o);
    int lane = threadIdx.x & 31, w = threadIdx.x >> 5;
    if (lane == 0) red[w] = v;
    __syncthreads();
    if (w == 0){
        v = (lane < 8) ? red[lane] : 0.f;
        #pragma unroll
        for (int o = 4; o; o >>= 1) v += __shfl_xor_sync(0xffffffffu, v, o);
    }
    return v;
}

__global__ void ln_kernel(const float* __restrict__ x, const float* __restrict__ g,
                          const float* __restrict__ b, __half* __restrict__ out){
    __shared__ float red[8];
    __shared__ float s_mu, s_rs;
    int row = blockIdx.x, tid = threadIdx.x;
    const float4 v = ((const float4*)(x + (size_t)row * Cc))[tid];
    float s = v.x + v.y + v.z + v.w;
    s = block_sum(s, red);
    if (tid == 0) s_mu = s * (1.0f / Cc);
    __syncthreads();
    float mu = s_mu;
    float dx = v.x - mu, dy = v.y - mu, dz = v.z - mu, dw = v.w - mu;
    float sq = dx*dx + dy*dy + dz*dz + dw*dw;
    sq = block_sum(sq, red);
    if (tid == 0) s_rs = rsqrtf(sq * (1.0f / Cc) + 1e-5f);
    __syncthreads();
    float rs = s_rs;
    float4 gg = ((const float4*)g)[tid], bb = ((const float4*)b)[tid];
    __half2 h0 = __floats2half2_rn(dx * rs * gg.x + bb.x, dy * rs * gg.y + bb.y);
    __half2 h1 = __floats2half2_rn(dz * rs * gg.z + bb.z, dw * rs * gg.w + bb.w);
    __half2* op = (__half2*)(out + (size_t)row * Cc);
    op[tid*2]     = h0;
    op[tid*2 + 1] = h1;
}

// ======================== fp16 tensor GEMM, cp.async 4-stage ========================
#define HSTR 40
#define NSTG 4
#define STG_H (128*HSTR)
#define GH_SMEM (NSTG * STG_H * 2 * 2)

#define CPA16(dst, src) \
    asm volatile("cp.async.cg.shared.global [%0], [%1], 16;" :: "r"(dst), "l"(src) : "memory")

template<bool OUT_HALF>
__global__ __launch_bounds__(256) void gemm_h(
        const __half* __restrict__ A,
        const __half* __restrict__ Bt,
        const float* __restrict__ bias,
        const float* __restrict__ resid,
        void* __restrict__ outv,
        int N, int K, int do_gelu){
    extern __shared__ __half smh[];
    __half* As = smh;
    __half* Bs = smh + NSTG * STG_H;
    const int tid = threadIdx.x;
    const int lane = tid & 31, w = tid >> 5;
    const int warpM = (w & 1) * 64, warpN = (w >> 1) * 32;
    const int row0 = blockIdx.y * 128, col0 = blockIdx.x * 128;

    const int sr = tid >> 1;
    const int kh = (tid & 1) * 16;
    const __half* Ap = A + (size_t)(row0 + sr) * K + kh;
    const __half* Bp = Bt + (size_t)(col0 + sr) * K + kh;
    const uint32_t adst = (uint32_t)__cvta_generic_to_shared(&As[sr*HSTR + kh]);
    const uint32_t bdst = (uint32_t)__cvta_generic_to_shared(&Bs[sr*HSTR + kh]);

    auto load_chunk = [&](int c, int s){
        uint32_t ao = adst + s * STG_H * 2;
        uint32_t bo = bdst + s * STG_H * 2;
        const __half* ag = Ap + c * 32;
        const __half* bg = Bp + c * 32;
        CPA16(ao, ag); CPA16(ao + 16, ag + 8);
        CPA16(bo, bg); CPA16(bo + 16, bg + 8);
        asm volatile("cp.async.commit_group;" ::: "memory");
    };

    float acc[4][4][4] = {};

    const int a_row = lane & 15;
    const int a_col = (lane >> 4) * 8;
    const int b_row = (lane & 7) + ((lane >> 4) << 3);
    const int b_col = ((lane >> 3) & 1) * 8;

    auto compute = [&](int s){
        const __half* Ab = As + s * STG_H;
        const __half* Bb2 = Bs + s * STG_H;
        #pragma unroll
        for (int kk = 0; kk < 2; kk++){
            uint32_t afr[4][4];
            #pragma unroll
            for (int mt = 0; mt < 4; mt++){
                uint32_t addr = (uint32_t)__cvta_generic_to_shared(
                    &Ab[(warpM + mt*16 + a_row) * HSTR + kk*16 + a_col]);
                asm volatile("ldmatrix.sync.aligned.m8n8.x4.shared.b16 {%0,%1,%2,%3}, [%4];"
                    : "=r"(afr[mt][0]), "=r"(afr[mt][1]), "=r"(afr[mt][2]), "=r"(afr[mt][3])
                    : "r"(addr));
            }
            uint32_t bfr[2][4];
            #pragma unroll
            for (int ng = 0; ng < 2; ng++){
                uint32_t addr = (uint32_t)__cvta_generic_to_shared(
                    &Bb2[(warpN + ng*16 + b_row) * HSTR + kk*16 + b_col]);
                asm volatile("ldmatrix.sync.aligned.m8n8.x4.shared.b16 {%0,%1,%2,%3}, [%4];"
                    : "=r"(bfr[ng][0]), "=r"(bfr[ng][1]), "=r"(bfr[ng][2]), "=r"(bfr[ng][3])
                    : "r"(addr));
            }
            #pragma unroll
            for (int mt = 0; mt < 4; mt++)
                #pragma unroll
                for (int nt = 0; nt < 4; nt++){
                    uint32_t b0 = bfr[nt >> 1][(nt & 1) * 2];
                    uint32_t b1 = bfr[nt >> 1][(nt & 1) * 2 + 1];
                    asm volatile(
                        "mma.sync.aligned.m16n8k16.row.col.f32.f16.f16.f32 "
                        "{%0,%1,%2,%3},{%4,%5,%6,%7},{%8,%9},{%0,%1,%2,%3};"
                        : "+f"(acc[mt][nt][0]), "+f"(acc[mt][nt][1]),
                          "+f"(acc[mt][nt][2]), "+f"(acc[mt][nt][3])
                        : "r"(afr[mt][0]), "r"(afr[mt][1]), "r"(afr[mt][2]), "r"(afr[mt][3]),
                          "r"(b0), "r"(b1));
                }
        }
    };

    const int ntiles = K / 32;
    load_chunk(0, 0); load_chunk(1, 1); load_chunk(2, 2);
    for (int t = 0; t < ntiles; t++){
        asm volatile("cp.async.wait_group 2;" ::: "memory");
        __syncthreads();
        if (t + 3 < ntiles) load_chunk(t + 3, (t + 3) & 3);
        compute(t & 3);
    }

    #pragma unroll
    for (int mt = 0; mt < 4; mt++){
        #pragma unroll
        for (int nt = 0; nt < 4; nt++){
            int rr = row0 + warpM + mt*16 + (lane >> 2);
            int cc = col0 + warpN + nt*8 + (lane & 3) * 2;
            #pragma unroll
            for (int half = 0; half < 2; half++){
                int r = rr + half * 8;
                float v0 = acc[mt][nt][half*2]     + bias[cc];
                float v1 = acc[mt][nt][half*2 + 1] + bias[cc + 1];
                if (resid){
                    const float2 rv = *(const float2*)&resid[(size_t)r * N + cc];
                    v0 += rv.x; v1 += rv.y;
                }
                if (do_gelu){
                    v0 = 0.5f * v0 * (1.f + erff(v0 * 0.70710678118f));
                    v1 = 0.5f * v1 * (1.f + erff(v1 * 0.70710678118f));
                }
                if (OUT_HALF){
                    *(__half2*)&((__half*)outv)[(size_t)r * N + cc] = __floats2half2_rn(v0, v1);
                } else {
                    *(float2*)&((float*)outv)[(size_t)r * N + cc] = make_float2(v0, v1);
                }
            }
        }
    }
}

// ======================== Attention: all-fp16 MMA + online max ========================
// smem: PsH half[128][72] (Q staging, then P), EsH half[64][72], VtH half[64][72]
#define HQ 72
#define QVLD (2*Cc)
#define ATTN_SMEM ((128 + 64 + 64) * HQ * 2)

__device__ __forceinline__ float lif_s(float I){
    // score = rate/8 ; 0 if I <= vth
    if (I > 1.0000001f){
        float u = __fdividef(1.0f, I);
        float d = fmaf(-0.02f, __logf(1.0f - u), 0.002f);
        return __fdividef(0.125f, d);
    }
    return 0.0f;
}

__global__ __launch_bounds__(256) void attn_tc(
        const __half* __restrict__ Q, const __half* __restrict__ V,
        const float* __restrict__ E, const float* __restrict__ gain,
        const float* __restrict__ bias, __half* __restrict__ out){
    extern __shared__ __half smh[];
    __half* PsH = smh;                    // 128*72
    __half* EsH = smh + 128*HQ;           // 64*72
    __half* VtH = smh + (128 + 64)*HQ;    // 64*72

    const int tid = threadIdx.x;
    const int lane = tid & 31, w = tid >> 5;
    const int bh = blockIdx.y, b = bh >> 4, h = bh & 15;
    const int t0 = (gridDim.x - 1 - blockIdx.x) << 7;
    const int rowbase = w << 4;

    const int a_row = lane & 15;
    const int a_col = (lane >> 4) * 8;
    const int b_row = (lane & 7) + ((lane >> 4) << 3);
    const int b_col = ((lane >> 3) & 1) * 8;

    // ---- stage Q tile (half copy)
    {
        const int qr = tid >> 1, qc = (tid & 1) * 32;
        const __half* qp = Q + ((size_t)(b*Tt + t0 + qr)) * QVLD + h*Dd + qc;
        #pragma unroll
        for (int j = 0; j < 4; j++)
            *(uint4*)&PsH[qr*HQ + qc + j*8] = *(const uint4*)(qp + j*8);
    }
    __syncthreads();

    uint32_t qa[4][4];
    #pragma unroll
    for (int kk = 0; kk < 4; kk++){
        uint32_t addr = (uint32_t)__cvta_generic_to_shared(
            &PsH[(rowbase + a_row) * HQ + kk*16 + a_col]);
        asm volatile("ldmatrix.sync.aligned.m8n8.x4.shared.b16 {%0,%1,%2,%3}, [%4];"
            : "=r"(qa[kk][0]), "=r"(qa[kk][1]), "=r"(qa[kk][2]), "=r"(qa[kk][3])
            : "r"(addr));
    }

    const int r = lane >> 2;
    const int cq = (lane & 3) << 1;
    const int tA = t0 + rowbase + r;
    const int tB = tA + 8;
    const float gA = gain[h*Tt + tA], bA = bias[h*Tt + tA];
    const float gB = gain[h*Tt + tB], bB = bias[h*Tt + tB];
    const int twmax = t0 + rowbase + 15;

    float oacc[8][4] = {};
    float psumA = 0.f, psumB = 0.f;
    float mA = 0.f, mB = 0.f;        // scores >= 0 always; diagonal guarantees max >= 0

    for (int s0 = 0; s0 < t0 + 128; s0 += 64){
        __syncthreads();
        // ---- stage E (half) and V^T (half)
        {
            const int lr = tid >> 2, cg = (tid & 3) * 16;
            const float* ep = E + ((size_t)(h*Tt + s0 + lr)) * Dd + cg;
            uint32_t hp[8];
            #pragma unroll
            for (int j = 0; j < 4; j++){
                float4 v4 = *(const float4*)(ep + j*4);
                __half2 lo = __floats2half2_rn(v4.x, v4.y);
                __half2 hi = __floats2half2_rn(v4.z, v4.w);
                hp[j*2]   = *(uint32_t*)&lo;
                hp[j*2+1] = *(uint32_t*)&hi;
            }
            *(uint4*)&EsH[lr*HQ + cg]     = make_uint4(hp[0], hp[1], hp[2], hp[3]);
            *(uint4*)&EsH[lr*HQ + cg + 8] = make_uint4(hp[4], hp[5], hp[6], hp[7]);

            const __half* vp = V + ((size_t)(b*Tt + s0 + lr)) * QVLD + h*Dd + cg;
            uint4 u0 = *(const uint4*)vp;
            uint4 u1 = *(const uint4*)(vp + 8);
            const __half* hv = (const __half*)&u0;
            #pragma unroll
            for (int j = 0; j < 8; j++)
                VtH[(cg + j)*HQ + lr] = hv[j];
            const __half* hv2 = (const __half*)&u1;
            #pragma unroll
            for (int j = 0; j < 8; j++)
                VtH[(cg + 8 + j)*HQ + lr] = hv2[j];
        }
        __syncthreads();

        if (s0 > twmax) continue;

        // ---- MMA1 fp16: S = Q . E^T
        float sacc[8][4] = {};
        #pragma unroll
        for (int kk = 0; kk < 4; kk++){
            uint32_t bfr[4][4];
            #pragma unroll
            for (int ng = 0; ng < 4; ng++){
                uint32_t addr = (uint32_t)__cvta_generic_to_shared(
                    &EsH[(ng*16 + b_row) * HQ + kk*16 + b_col]);
                asm volatile("ldmatrix.sync.aligned.m8n8.x4.shared.b16 {%0,%1,%2,%3}, [%4];"
                    : "=r"(bfr[ng][0]), "=r"(bfr[ng][1]), "=r"(bfr[ng][2]), "=r"(bfr[ng][3])
                    : "r"(addr));
            }
            #pragma unroll
            for (int nt = 0; nt < 8; nt++){
                uint32_t b0 = bfr[nt >> 1][(nt & 1) * 2];
                uint32_t b1 = bfr[nt >> 1][(nt & 1) * 2 + 1];
                asm volatile(
                    "mma.sync.aligned.m16n8k16.row.col.f32.f16.f16.f32 "
                    "{%0,%1,%2,%3},{%4,%5,%6,%7},{%8,%9},{%0,%1,%2,%3};"
                    : "+f"(sacc[nt][0]), "+f"(sacc[nt][1]),
                      "+f"(sacc[nt][2]), "+f"(sacc[nt][3])
                    : "r"(qa[kk][0]), "r"(qa[kk][1]), "r"(qa[kk][2]), "r"(qa[kk][3]),
                      "r"(b0), "r"(b1));
            }
        }

        // ---- scores + causal mask (keep raw scores; exp after max update)
        float tmaxA = 0.f, tmaxB = 0.f;
        #pragma unroll
        for (int nt = 0; nt < 8; nt++){
            int sb = s0 + nt*8 + cq;
            float v00 = (sb     <= tA) ? lif_s(fmaf(gA, sacc[nt][0], bA)) : -1e30f;
            float v01 = (sb + 1 <= tA) ? lif_s(fmaf(gA, sacc[nt][1], bA)) : -1e30f;
            float v10 = (sb     <= tB) ? lif_s(fmaf(gB, sacc[nt][2], bB)) : -1e30f;
            float v11 = (sb + 1 <= tB) ? lif_s(fmaf(gB, sacc[nt][3], bB)) : -1e30f;
            sacc[nt][0] = v00; sacc[nt][1] = v01; sacc[nt][2] = v10; sacc[nt][3] = v11;
            tmaxA = fmaxf(tmaxA, fmaxf(v00, v01));
            tmaxB = fmaxf(tmaxB, fmaxf(v10, v11));
        }
        tmaxA = fmaxf(tmaxA, __shfl_xor_sync(0xffffffffu, tmaxA, 1));
        tmaxA = fmaxf(tmaxA, __shfl_xor_sync(0xffffffffu, tmaxA, 2));
        tmaxB = fmaxf(tmaxB, __shfl_xor_sync(0xffffffffu, tmaxB, 1));
        tmaxB = fmaxf(tmaxB, __shfl_xor_sync(0xffffffffu, tmaxB, 2));

        float mAn = fmaxf(mA, tmaxA), mBn = fmaxf(mB, tmaxB);
        float scA = __expf(mA - mAn), scB = __expf(mB - mBn);
        mA = mAn; mB = mBn;
        psumA *= scA; psumB *= scB;
        #pragma unroll
        for (int nt = 0; nt < 8; nt++){
            oacc[nt][0] *= scA; oacc[nt][1] *= scA;
            oacc[nt][2] *= scB; oacc[nt][3] *= scB;
        }

        #pragma unroll
        for (int nt = 0; nt < 8; nt++){
            float p00 = __expf(sacc[nt][0] - mAn);
            float p01 = __expf(sacc[nt][1] - mAn);
            float p10 = __expf(sacc[nt][2] - mBn);
            float p11 = __expf(sacc[nt][3] - mBn);
            psumA += p00 + p01;
            psumB += p10 + p11;
            *(__half2*)&PsH[(rowbase + r    )*HQ + nt*8 + cq] = __floats2half2_rn(p00, p01);
            *(__half2*)&PsH[(rowbase + r + 8)*HQ + nt*8 + cq] = __floats2half2_rn(p10, p11);
        }
        __syncwarp();

        // ---- MMA2 fp16: O += P . V
        #pragma unroll
        for (int kk = 0; kk < 4; kk++){
            uint32_t afr[4];
            {
                uint32_t addr = (uint32_t)__cvta_generic_to_shared(
                    &PsH[(rowbase + a_row) * HQ + kk*16 + a_col]);
                asm volatile("ldmatrix.sync.aligned.m8n8.x4.shared.b16 {%0,%1,%2,%3}, [%4];"
                    : "=r"(afr[0]), "=r"(afr[1]), "=r"(afr[2]), "=r"(afr[3])
                    : "r"(addr));
            }
            uint32_t bfr[4][4];
            #pragma unroll
            for (int ng = 0; ng < 4; ng++){
                uint32_t addr = (uint32_t)__cvta_generic_to_shared(
                    &VtH[(ng*16 + b_row) * HQ + kk*16 + b_col]);
                asm volatile("ldmatrix.sync.aligned.m8n8.x4.shared.b16 {%0,%1,%2,%3}, [%4];"
                    : "=r"(bfr[ng][0]), "=r"(bfr[ng][1]), "=r"(bfr[ng][2]), "=r"(bfr[ng][3])
                    : "r"(addr));
            }
            #pragma unroll
            for (int nt = 0; nt < 8; nt++){
                uint32_t b0 = bfr[nt >> 1][(nt & 1) * 2];
                uint32_t b1 = bfr[nt >> 1][(nt & 1) * 2 + 1];
                asm volatile(
                    "mma.sync.aligned.m16n8k16.row.col.f32.f16.f16.f32 "
                    "{%0,%1,%2,%3},{%4,%5,%6,%7},{%8,%9},{%0,%1,%2,%3};"
                    : "+f"(oacc[nt][0]), "+f"(oacc[nt][1]),
                      "+f"(oacc[nt][2]), "+f"(oacc[nt][3])
                    : "r"(afr[0]), "r"(afr[1]), "r"(afr[2]), "r"(afr[3]),
                      "r"(b0), "r"(b1));
            }
        }
    }

    psumA += __shfl_xor_sync(0xffffffffu, psumA, 1);
    psumA += __shfl_xor_sync(0xffffffffu, psumA, 2);
    psumB += __shfl_xor_sync(0xffffffffu, psumB, 1);
    psumB += __shfl_xor_sync(0xffffffffu, psumB, 2);
    float invA = 1.0f / psumA;
    float invB = 1.0f / psumB;

    __half* opA = out + ((size_t)(b*Tt + tA)) * Cc + h*Dd;
    __half* opB = out + ((size_t)(b*Tt + tB)) * Cc + h*Dd;
    #pragma unroll
    for (int nt = 0; nt < 8; nt++){
        int d = nt*8 + cq;
        *(__half2*)&opA[d] = __floats2half2_rn(oacc[nt][0]*invA, oacc[nt][1]*invA);
        *(__half2*)&opB[d] = __floats2half2_rn(oacc[nt][2]*invB, oacc[nt][3]*invB);
    }
}

// ======================== launch ========================
extern "C" void kernel_launch(void* const* d_in, const int* in_sizes, int n_in,
                              void* d_out, int out_size){
    const float* x      = (const float*)d_in[0];
    const float* ln1_g  = (const float*)d_in[1];
    const float* ln1_b  = (const float*)d_in[2];
    const float* qkv_w  = (const float*)d_in[3];
    const float* qkv_b  = (const float*)d_in[4];
    const float* out_w  = (const float*)d_in[5];
    const float* out_b  = (const float*)d_in[6];
    const float* ln2_g  = (const float*)d_in[7];
    const float* ln2_b  = (const float*)d_in[8];
    const float* mlp_w1 = (const float*)d_in[9];
    const float* mlp_b1 = (const float*)d_in[10];
    const float* mlp_w2 = (const float*)d_in[11];
    const float* mlp_b2 = (const float*)d_in[12];
    const float* enc    = (const float*)d_in[13];
    const float* gain   = (const float*)d_in[14];
    const float* battn  = (const float*)d_in[15];
    float* outp = (float*)d_out;

    __half *xn, *qv, *att, *hbuf, *wqv, *wo, *w1, *w2;
    float *x1, *qvb;
    cudaGetSymbolAddress((void**)&xn,   g_xn);
    cudaGetSymbolAddress((void**)&qv,   g_qv);
    cudaGetSymbolAddress((void**)&att,  g_att);
    cudaGetSymbolAddress((void**)&x1,   g_x1);
    cudaGetSymbolAddress((void**)&hbuf, g_h);
    cudaGetSymbolAddress((void**)&wqv,  g_wqv);
    cudaGetSymbolAddress((void**)&wo,   g_wo);
    cudaGetSymbolAddress((void**)&w1,   g_w1);
    cudaGetSymbolAddress((void**)&w2,   g_w2);
    cudaGetSymbolAddress((void**)&qvb,  g_qvb);

    cudaFuncSetAttribute(attn_tc,       cudaFuncAttributeMaxDynamicSharedMemorySize, ATTN_SMEM);
    cudaFuncSetAttribute(gemm_h<true>,  cudaFuncAttributeMaxDynamicSharedMemorySize, GH_SMEM);
    cudaFuncSetAttribute(gemm_h<false>, cudaFuncAttributeMaxDynamicSharedMemorySize, GH_SMEM);

    const int M = Bb * Tt;

    pack_bias<<<8, 256>>>(qkv_b, qvb);
    transpose_h<<<dim3(Cc/32,   Cc/32),   dim3(32,8)>>>(qkv_w,        3*Cc, wqv,         Cc);
    transpose_h<<<dim3(Cc/32,   Cc/32),   dim3(32,8)>>>(qkv_w + 2*Cc, 3*Cc, wqv + Cc*Cc, Cc);
    transpose_h<<<dim3(Cc/32,   Cc/32),   dim3(32,8)>>>(out_w,        Cc,   wo,          Cc);
    transpose_h<<<dim3(4*Cc/32, Cc/32),   dim3(32,8)>>>(mlp_w1,       4*Cc, w1,          Cc);
    transpose_h<<<dim3(Cc/32,   4*Cc/32), dim3(32,8)>>>(mlp_w2,       Cc,   w2,          4*Cc);

    ln_kernel<<<M, 256>>>(x, ln1_g, ln1_b, xn);
    gemm_h<true ><<<dim3(2*Cc/128, M/128), 256, GH_SMEM>>>(xn, wqv, qvb, nullptr, qv, 2*Cc, Cc, 0);
    attn_tc<<<dim3(Tt/128, Bb*Hh), 256, ATTN_SMEM>>>(qv, qv + Cc, enc, gain, battn, att);
    gemm_h<false><<<dim3(Cc/128, M/128), 256, GH_SMEM>>>(att, wo, out_b, x, x1, Cc, Cc, 0);
    ln_kernel<<<M, 256>>>(x1, ln2_g, ln2_b, xn);
    gemm_h<true ><<<dim3(4*Cc/128, M/128), 256, GH_SMEM>>>(xn, w1, mlp_b1, nullptr, hbuf, 4*Cc, Cc, 1);
    gemm_h<false><<<dim3(Cc/128, M/128), 256, GH_SMEM>>>(hbuf, w2, mlp_b2, x1, outp, Cc, 4*Cc, 0);
}